// round 1
// baseline (speedup 1.0000x reference)
#include <cuda_runtime.h>
#include <cuda_bf16.h>

#define HID   1024
#define NH    16
#define HD    64
#define BATCH 4
#define SEQ   2048
#define MTOT  (BATCH*SEQ)   // 8192

// Scratch (allocation-free rule: __device__ globals). 4 x 32MB.
__device__ float g_Q[(size_t)MTOT * HID];  // [B,H,S,D]
__device__ float g_K[(size_t)MTOT * HID];  // [B,H,S,D]
__device__ float g_V[(size_t)MTOT * HID];  // [B,H,S,D]
__device__ float g_X[(size_t)MTOT * HID];  // [B,S,HID] attention output

// ---------------------------------------------------------------------------
// Tiled fp32 GEMM:  out[m,n] = sum_k X[m,k] * W[n,k] + bias[n]
// M=8192, N=K=1024. BM=BN=64, BK=16, 256 threads, 4x4 micro-tile.
// which: 0/1/2 -> scatter into g_Q/g_K/g_V as [B,H,S,D]; 3 -> read g_X, write
// `out` plain row-major.
// ---------------------------------------------------------------------------
__global__ __launch_bounds__(256) void gemm64(const float* __restrict__ X,
                                              const float* __restrict__ W,
                                              const float* __restrict__ bias,
                                              float* __restrict__ out,
                                              int which)
{
    __shared__ float As[16 * 68];   // As[k][m], stride 68 keeps float4 aligned
    __shared__ float Bs[16 * 68];   // Bs[k][n] = W[n,k]

    const float* Xp   = (which == 3) ? g_X : X;
    float*       outp = (which == 0) ? g_Q
                      : (which == 1) ? g_K
                      : (which == 2) ? g_V : out;

    const int tid  = threadIdx.x;
    const int tx   = tid & 15;
    const int ty   = tid >> 4;
    const int m0   = blockIdx.y * 64;
    const int n0   = blockIdx.x * 64;
    const int lrow = tid >> 2;        // 0..63
    const int lcol = (tid & 3) << 2;  // 0,4,8,12

    const float* xg = Xp + (size_t)(m0 + lrow) * HID + lcol;
    const float* wg = W  + (size_t)(n0 + lrow) * HID + lcol;

    float acc[4][4] = {};

    for (int k0 = 0; k0 < HID; k0 += 16) {
        float4 xa = *(const float4*)(xg + k0);
        float4 wb = *(const float4*)(wg + k0);
        As[(lcol + 0) * 68 + lrow] = xa.x;
        As[(lcol + 1) * 68 + lrow] = xa.y;
        As[(lcol + 2) * 68 + lrow] = xa.z;
        As[(lcol + 3) * 68 + lrow] = xa.w;
        Bs[(lcol + 0) * 68 + lrow] = wb.x;
        Bs[(lcol + 1) * 68 + lrow] = wb.y;
        Bs[(lcol + 2) * 68 + lrow] = wb.z;
        Bs[(lcol + 3) * 68 + lrow] = wb.w;
        __syncthreads();

        #pragma unroll
        for (int kk = 0; kk < 16; kk++) {
            float4 av = *(const float4*)&As[kk * 68 + ty * 4];
            float4 bv = *(const float4*)&Bs[kk * 68 + tx * 4];
            float a4[4] = {av.x, av.y, av.z, av.w};
            float b4[4] = {bv.x, bv.y, bv.z, bv.w};
            #pragma unroll
            for (int i = 0; i < 4; i++)
                #pragma unroll
                for (int j = 0; j < 4; j++)
                    acc[i][j] += a4[i] * b4[j];
        }
        __syncthreads();
    }

    #pragma unroll
    for (int i = 0; i < 4; i++) {
        const int m = m0 + ty * 4 + i;
        #pragma unroll
        for (int j = 0; j < 4; j++) {
            const int n = n0 + tx * 4 + j;
            const float v = acc[i][j] + bias[n];
            if (which < 3) {
                const int b = m >> 11, s = m & 2047;
                const int h = n >> 6,  d = n & 63;
                outp[((size_t)((b * NH + h) * SEQ + s)) * HD + d] = v;
            } else {
                outp[(size_t)m * HID + n] = v;
            }
        }
    }
}

// ---------------------------------------------------------------------------
// Flash attention, fp32, head_dim=64. One block per (bh, 64-row q tile).
// 256 threads, each owns a 4x4 patch of the 64x64 S tile and of the 64x64 O
// tile. Online softmax in base 2. P goes through smem (transposed) so the PV
// GEMM uses the same conflict-free float4 pattern as QK^T.
// ---------------------------------------------------------------------------
__global__ __launch_bounds__(256) void attn64()
{
    extern __shared__ float sm[];
    float* Qs = sm;              // Qs[d*68 + q]   (d-major)
    float* Ks = sm + 64 * 68;    // Ks[d*68 + k]   (d-major)
    float* Vs = sm + 2 * 64 * 68;// Vs[k*68 + d]   (natural)
    float* Ps = sm + 3 * 64 * 68;// Ps[k*68 + q]   (k-major)

    const int tid = threadIdx.x;
    const int tx  = tid & 15;
    const int ty  = tid >> 4;
    const int q0  = blockIdx.x * 64;
    const int bh  = blockIdx.y;

    const float* Qg = g_Q + (size_t)bh * SEQ * HD;
    const float* Kg = g_K + (size_t)bh * SEQ * HD;
    const float* Vg = g_V + (size_t)bh * SEQ * HD;

    const int lrow = tid >> 2;   // 0..63
    const int lseg = tid & 3;    // 0..3

    // Load Q tile, transposed to d-major
    #pragma unroll
    for (int c = 0; c < 4; c++) {
        const int d0 = lseg * 16 + c * 4;
        float4 v = *(const float4*)(Qg + (size_t)(q0 + lrow) * HD + d0);
        Qs[(d0 + 0) * 68 + lrow] = v.x;
        Qs[(d0 + 1) * 68 + lrow] = v.y;
        Qs[(d0 + 2) * 68 + lrow] = v.z;
        Qs[(d0 + 3) * 68 + lrow] = v.w;
    }

    float o[4][4] = {};
    float mrun[4], lrun[4];
    #pragma unroll
    for (int i = 0; i < 4; i++) { mrun[i] = -1e30f; lrun[i] = 0.f; }

    __syncthreads();

    const float csc = 0.125f * 1.44269504f;  // 1/sqrt(64) * log2(e)

    for (int kt = 0; kt < SEQ; kt += 64) {
        // Load K (transposed) + V (natural)
        #pragma unroll
        for (int c = 0; c < 4; c++) {
            const int d0 = lseg * 16 + c * 4;
            float4 kv = *(const float4*)(Kg + (size_t)(kt + lrow) * HD + d0);
            Ks[(d0 + 0) * 68 + lrow] = kv.x;
            Ks[(d0 + 1) * 68 + lrow] = kv.y;
            Ks[(d0 + 2) * 68 + lrow] = kv.z;
            Ks[(d0 + 3) * 68 + lrow] = kv.w;
            float4 vv = *(const float4*)(Vg + (size_t)(kt + lrow) * HD + d0);
            *(float4*)&Vs[lrow * 68 + d0] = vv;
        }
        __syncthreads();

        // S = Q @ K^T  (base-2 logits after scaling)
        float t[4][4] = {};
        #pragma unroll 16
        for (int d = 0; d < 64; d++) {
            float4 av = *(const float4*)&Qs[d * 68 + ty * 4];
            float4 bv = *(const float4*)&Ks[d * 68 + tx * 4];
            float a4[4] = {av.x, av.y, av.z, av.w};
            float b4[4] = {bv.x, bv.y, bv.z, bv.w};
            #pragma unroll
            for (int i = 0; i < 4; i++)
                #pragma unroll
                for (int j = 0; j < 4; j++)
                    t[i][j] += a4[i] * b4[j];
        }

        // Online softmax (rows reduced across the 16-lane tx group)
        float p[4][4];
        #pragma unroll
        for (int i = 0; i < 4; i++) {
            float tm = -1e30f;
            #pragma unroll
            for (int j = 0; j < 4; j++) { t[i][j] *= csc; tm = fmaxf(tm, t[i][j]); }
            #pragma unroll
            for (int off = 8; off; off >>= 1)
                tm = fmaxf(tm, __shfl_xor_sync(0xffffffffu, tm, off));
            const float mn   = fmaxf(mrun[i], tm);
            const float corr = exp2f(mrun[i] - mn);
            float rs = 0.f;
            #pragma unroll
            for (int j = 0; j < 4; j++) { p[i][j] = exp2f(t[i][j] - mn); rs += p[i][j]; }
            #pragma unroll
            for (int off = 8; off; off >>= 1)
                rs += __shfl_xor_sync(0xffffffffu, rs, off);
            lrun[i] = lrun[i] * corr + rs;
            mrun[i] = mn;
            #pragma unroll
            for (int j = 0; j < 4; j++) o[i][j] *= corr;
        }

        // Store P transposed (k-major)
        #pragma unroll
        for (int j = 0; j < 4; j++)
            #pragma unroll
            for (int i = 0; i < 4; i++)
                Ps[(tx * 4 + j) * 68 + ty * 4 + i] = p[i][j];
        __syncthreads();

        // O += P @ V
        #pragma unroll 16
        for (int k = 0; k < 64; k++) {
            float4 av = *(const float4*)&Ps[k * 68 + ty * 4];
            float4 bv = *(const float4*)&Vs[k * 68 + tx * 4];
            float a4[4] = {av.x, av.y, av.z, av.w};
            float b4[4] = {bv.x, bv.y, bv.z, bv.w};
            #pragma unroll
            for (int i = 0; i < 4; i++)
                #pragma unroll
                for (int j = 0; j < 4; j++)
                    o[i][j] += a4[i] * b4[j];
        }
        __syncthreads();
    }

    // Normalize + write O as [B,S,HID]
    const int b = bh >> 4, h = bh & 15;
    #pragma unroll
    for (int i = 0; i < 4; i++) {
        const float inv = 1.f / lrun[i];
        const int q = q0 + ty * 4 + i;
        float4 w;
        w.x = o[i][0] * inv; w.y = o[i][1] * inv;
        w.z = o[i][2] * inv; w.w = o[i][3] * inv;
        *(float4*)(g_X + (size_t)(b * SEQ + q) * HID + h * HD + tx * 4) = w;
    }
}

// ---------------------------------------------------------------------------
extern "C" void kernel_launch(void* const* d_in, const int* in_sizes, int n_in,
                              void* d_out, int out_size)
{
    const float* query = (const float*)d_in[0];
    const float* key   = (const float*)d_in[1];
    const float* value = (const float*)d_in[2];
    const float* wq    = (const float*)d_in[3];
    const float* bq    = (const float*)d_in[4];
    const float* wk    = (const float*)d_in[5];
    const float* bk    = (const float*)d_in[6];
    const float* wv    = (const float*)d_in[7];
    const float* bv    = (const float*)d_in[8];
    const float* wf    = (const float*)d_in[9];
    const float* bf    = (const float*)d_in[10];
    float* out = (float*)d_out;

    // Dynamic smem for attention (69632 B > 48KB default). Immediate API,
    // idempotent, graph-capture safe (not a stream op).
    cudaFuncSetAttribute(attn64, cudaFuncAttributeMaxDynamicSharedMemorySize,
                         4 * 64 * 68 * 4);

    dim3 gg(HID / 64, MTOT / 64);   // (16, 128)
    gemm64<<<gg, 256>>>(query, wq, bq, nullptr, 0);
    gemm64<<<gg, 256>>>(key,   wk, bk, nullptr, 1);
    gemm64<<<gg, 256>>>(value, wv, bv, nullptr, 2);

    dim3 ga(SEQ / 64, BATCH * NH);  // (32, 64)
    attn64<<<ga, 256, 4 * 64 * 68 * 4>>>();

    gemm64<<<gg, 256>>>(nullptr, wf, bf, out, 3);
}

// round 3
// speedup vs baseline: 1.8932x; 1.8932x over previous
#include <cuda_runtime.h>
#include <cuda_bf16.h>
#include <cstdint>

#define HID   1024
#define NH    16
#define HD    64
#define BATCH 4
#define SEQ   2048
#define MTOT  (BATCH*SEQ)   // 8192

// Scratch (allocation-free rule: __device__ globals).
__device__ float g_Q[(size_t)MTOT * HID];  // [B,H,S,D]
__device__ float g_K[(size_t)MTOT * HID];  // [B,H,S,D]
__device__ float g_V[(size_t)MTOT * HID];  // [B,H,S,D]
__device__ float g_X[(size_t)MTOT * HID];  // [B,S,HID] attention output

// ---------------------------------------------------------------------------
// tf32 helpers (base-target PTX: works under compute_103)
// ---------------------------------------------------------------------------
static __device__ __forceinline__ uint32_t f2tf(float x) {
    uint32_t r;
    asm("cvt.rna.tf32.f32 %0, %1;" : "=r"(r) : "f"(x));
    return r;
}
// D += A*B  (m16n8k8, tf32 inputs, f32 accum)
static __device__ __forceinline__ void mma8(float* d, const uint32_t* a,
                                            uint32_t b0, uint32_t b1) {
    asm volatile(
        "mma.sync.aligned.m16n8k8.row.col.f32.tf32.tf32.f32 "
        "{%0,%1,%2,%3}, {%4,%5,%6,%7}, {%8,%9}, {%0,%1,%2,%3};"
        : "+f"(d[0]), "+f"(d[1]), "+f"(d[2]), "+f"(d[3])
        : "r"(a[0]), "r"(a[1]), "r"(a[2]), "r"(a[3]), "r"(b0), "r"(b1));
}
static __device__ __forceinline__ uint32_t fbits(float x) { return __float_as_uint(x); }

// ---------------------------------------------------------------------------
// tf32 tensor-core GEMM:  out[m,n] = sum_k X[m,k]*W[n,k] + bias[n]
// CTA 128x128, BK=32, 256 thr (8 warps, 2m x 4n), warp tile 64x32.
// smem stride 36 words => frag pattern (4r+c) mod 32 conflict-free.
// which: 0/1/2 -> scatter into g_Q/g_K/g_V as [B,H,S,D]; 3 -> g_X -> out.
// ---------------------------------------------------------------------------
#define SA 36
#define GEMM_SMEM (2 * 2 * 128 * SA * 4)   // 73728 B

__global__ __launch_bounds__(256) void gemm_tc(const float* __restrict__ X,
                                               const float* __restrict__ W,
                                               const float* __restrict__ bias,
                                               float* __restrict__ out,
                                               int which)
{
    extern __shared__ float sm[];

    const float* Xp = (which == 3) ? g_X : X;
    float* outp = (which == 0) ? g_Q
                : (which == 1) ? g_K
                : (which == 2) ? g_V : out;

    const int tid  = threadIdx.x;
    const int wid  = tid >> 5;
    const int lane = tid & 31;
    const int wm   = wid >> 2;        // 0..1
    const int wn   = wid & 3;         // 0..3
    const int qr   = lane >> 2;       // 0..7
    const int qc   = lane & 3;        // 0..3
    const int m0   = blockIdx.y * 128;
    const int n0   = blockIdx.x * 128;

    const int lr = tid >> 3;          // 0..31
    const int lc = (tid & 7) << 2;    // 0..28
    const float* xg = Xp + (size_t)(m0 + lr) * HID + lc;
    const float* wg = W  + (size_t)(n0 + lr) * HID + lc;

    float4 xa[4], wb[4];
    auto gload = [&](int kc) {
        #pragma unroll
        for (int i = 0; i < 4; i++) {
            const size_t go = (size_t)(i * 32) * HID + kc * 32;
            xa[i] = *(const float4*)(xg + go);
            wb[i] = *(const float4*)(wg + go);
        }
    };
    auto sstore = [&](int buf) {
        float* A = sm + buf * 2 * 128 * SA;
        float* B = A + 128 * SA;
        #pragma unroll
        for (int i = 0; i < 4; i++) {
            const int r = lr + 32 * i;
            *(uint4*)(A + r * SA + lc) =
                make_uint4(f2tf(xa[i].x), f2tf(xa[i].y), f2tf(xa[i].z), f2tf(xa[i].w));
            *(uint4*)(B + r * SA + lc) =
                make_uint4(f2tf(wb[i].x), f2tf(wb[i].y), f2tf(wb[i].z), f2tf(wb[i].w));
        }
    };

    float acc[4][4][4] = {};

    gload(0); sstore(0);
    __syncthreads();

    const int NKC = HID / 32;   // 32
    for (int kc = 0; kc < NKC; kc++) {
        const int cur = kc & 1;
        if (kc + 1 < NKC) gload(kc + 1);

        const float* A = sm + cur * 2 * 128 * SA;
        const float* B = A + 128 * SA;
        #pragma unroll
        for (int ks = 0; ks < 4; ks++) {
            const int col = ks * 8 + qc;
            uint32_t af[4][4], bf[4][2];
            #pragma unroll
            for (int mt = 0; mt < 4; mt++) {
                const float* p = A + (wm * 64 + mt * 16 + qr) * SA + col;
                af[mt][0] = fbits(p[0]);
                af[mt][1] = fbits(p[8 * SA]);
                af[mt][2] = fbits(p[4]);
                af[mt][3] = fbits(p[8 * SA + 4]);
            }
            #pragma unroll
            for (int nt = 0; nt < 4; nt++) {
                const float* p = B + (wn * 32 + nt * 8 + qr) * SA + col;
                bf[nt][0] = fbits(p[0]);
                bf[nt][1] = fbits(p[4]);
            }
            #pragma unroll
            for (int mt = 0; mt < 4; mt++)
                #pragma unroll
                for (int nt = 0; nt < 4; nt++)
                    mma8(acc[mt][nt], af[mt], bf[nt][0], bf[nt][1]);
        }
        if (kc + 1 < NKC) sstore(cur ^ 1);
        __syncthreads();
    }

    // Epilogue
    #pragma unroll
    for (int mt = 0; mt < 4; mt++) {
        const int m = m0 + wm * 64 + mt * 16 + qr;
        #pragma unroll
        for (int nt = 0; nt < 4; nt++) {
            const int n = n0 + wn * 32 + nt * 8 + 2 * qc;
            const float b0 = bias[n], b1 = bias[n + 1];
            float2 v0 = make_float2(acc[mt][nt][0] + b0, acc[mt][nt][1] + b1);
            float2 v1 = make_float2(acc[mt][nt][2] + b0, acc[mt][nt][3] + b1);
            if (which < 3) {
                const int bb = m >> 11, h = n >> 6, d = n & 63;
                const int s0 = m & 2047;
                float* base = outp + ((size_t)(bb * NH + h) * SEQ) * HD + d;
                *(float2*)(base + (size_t)s0 * HD)       = v0;
                *(float2*)(base + (size_t)(s0 + 8) * HD) = v1;
            } else {
                *(float2*)(outp + (size_t)m * HID + n)       = v0;
                *(float2*)(outp + (size_t)(m + 8) * HID + n) = v1;
            }
        }
    }
}

// ---------------------------------------------------------------------------
// Flash attention on mma.sync tf32. Br=Bc=64, head_dim=64.
// 128 threads (4 warps); warp w owns q rows [w*16, w*16+16).
// smem stride 68 words => frag pattern conflict-free.
// ---------------------------------------------------------------------------
#define ST 68
#define ATTN_SMEM (4 * 64 * ST * 4)   // 69632 B

__global__ __launch_bounds__(128) void attn_tc()
{
    extern __shared__ float sm[];
    float* Qs = sm;                 // [64][ST]  Q[q][d]
    float* Ks = sm + 64 * ST;       // [64][ST]  K[kv][d]
    float* Vt = sm + 2 * 64 * ST;   // [64][ST]  V^T[d][kv]
    float* Ps = sm + 3 * 64 * ST;   // [64][ST]  P[q][kv]

    const int tid  = threadIdx.x;
    const int wid  = tid >> 5;
    const int lane = tid & 31;
    const int qr   = lane >> 2;
    const int qc   = lane & 3;
    const int q0   = blockIdx.x * 64;
    const int bh   = blockIdx.y;

    const float* Qg = g_Q + (size_t)bh * SEQ * HD;
    const float* Kg = g_K + (size_t)bh * SEQ * HD;
    const float* Vg = g_V + (size_t)bh * SEQ * HD;

    const int r8 = tid >> 4;          // 0..7
    const int c4 = (tid & 15) << 2;   // 0..60

    // Load Q (tf32-rounded)
    #pragma unroll
    for (int i = 0; i < 8; i++) {
        const int r = r8 + i * 8;
        float4 v = *(const float4*)(Qg + (size_t)(q0 + r) * HD + c4);
        *(uint4*)(Qs + r * ST + c4) =
            make_uint4(f2tf(v.x), f2tf(v.y), f2tf(v.z), f2tf(v.w));
    }
    __syncthreads();

    // Hoist Q fragments for the whole kernel (A of QK^T)
    uint32_t aq[8][4];
    {
        const float* p = Qs + (wid * 16 + qr) * ST;
        #pragma unroll
        for (int ks = 0; ks < 8; ks++) {
            const int col = ks * 8 + qc;
            aq[ks][0] = fbits(p[col]);
            aq[ks][1] = fbits(p[8 * ST + col]);
            aq[ks][2] = fbits(p[col + 4]);
            aq[ks][3] = fbits(p[8 * ST + col + 4]);
        }
    }

    float o[8][4] = {};
    float mr[2] = { -1e30f, -1e30f };
    float lr_[2] = { 0.f, 0.f };
    const float csc = 0.125f * 1.44269504f;  // 1/sqrt(64) * log2(e)

    for (int kt = 0; kt < SEQ; kt += 64) {
        __syncthreads();   // previous tile's reads complete
        #pragma unroll
        for (int i = 0; i < 8; i++) {
            const int r = r8 + i * 8;
            float4 kv = *(const float4*)(Kg + (size_t)(kt + r) * HD + c4);
            *(uint4*)(Ks + r * ST + c4) =
                make_uint4(f2tf(kv.x), f2tf(kv.y), f2tf(kv.z), f2tf(kv.w));
            float4 vv = *(const float4*)(Vg + (size_t)(kt + r) * HD + c4);
            uint32_t* vt = (uint32_t*)Vt;
            vt[(c4 + 0) * ST + r] = f2tf(vv.x);
            vt[(c4 + 1) * ST + r] = f2tf(vv.y);
            vt[(c4 + 2) * ST + r] = f2tf(vv.z);
            vt[(c4 + 3) * ST + r] = f2tf(vv.w);
        }
        __syncthreads();

        // S = Q @ K^T  -> s[nt][4] per thread
        float s[8][4] = {};
        #pragma unroll
        for (int ks = 0; ks < 8; ks++) {
            const int col = ks * 8 + qc;
            #pragma unroll
            for (int nt = 0; nt < 8; nt++) {
                const float* p = Ks + (nt * 8 + qr) * ST + col;
                mma8(s[nt], aq[ks], fbits(p[0]), fbits(p[4]));
            }
        }

        // Online softmax (rows qr and qr+8 of this warp's 16-row block)
        float tmax0 = -1e30f, tmax1 = -1e30f;
        #pragma unroll
        for (int nt = 0; nt < 8; nt++) {
            s[nt][0] *= csc; s[nt][1] *= csc; s[nt][2] *= csc; s[nt][3] *= csc;
            tmax0 = fmaxf(tmax0, fmaxf(s[nt][0], s[nt][1]));
            tmax1 = fmaxf(tmax1, fmaxf(s[nt][2], s[nt][3]));
        }
        tmax0 = fmaxf(tmax0, __shfl_xor_sync(0xffffffffu, tmax0, 1));
        tmax0 = fmaxf(tmax0, __shfl_xor_sync(0xffffffffu, tmax0, 2));
        tmax1 = fmaxf(tmax1, __shfl_xor_sync(0xffffffffu, tmax1, 1));
        tmax1 = fmaxf(tmax1, __shfl_xor_sync(0xffffffffu, tmax1, 2));
        const float mn0 = fmaxf(mr[0], tmax0);
        const float mn1 = fmaxf(mr[1], tmax1);
        const float corr0 = exp2f(mr[0] - mn0);
        const float corr1 = exp2f(mr[1] - mn1);
        mr[0] = mn0; mr[1] = mn1;

        float rs0 = 0.f, rs1 = 0.f;
        #pragma unroll
        for (int nt = 0; nt < 8; nt++) {
            s[nt][0] = exp2f(s[nt][0] - mn0);
            s[nt][1] = exp2f(s[nt][1] - mn0);
            s[nt][2] = exp2f(s[nt][2] - mn1);
            s[nt][3] = exp2f(s[nt][3] - mn1);
            rs0 += s[nt][0] + s[nt][1];
            rs1 += s[nt][2] + s[nt][3];
        }
        rs0 += __shfl_xor_sync(0xffffffffu, rs0, 1);
        rs0 += __shfl_xor_sync(0xffffffffu, rs0, 2);
        rs1 += __shfl_xor_sync(0xffffffffu, rs1, 1);
        rs1 += __shfl_xor_sync(0xffffffffu, rs1, 2);
        lr_[0] = lr_[0] * corr0 + rs0;
        lr_[1] = lr_[1] * corr1 + rs1;

        #pragma unroll
        for (int nt = 0; nt < 8; nt++) {
            o[nt][0] *= corr0; o[nt][1] *= corr0;
            o[nt][2] *= corr1; o[nt][3] *= corr1;
        }

        // Store P (tf32-rounded) into this warp's rows of Ps
        {
            uint32_t* P0 = (uint32_t*)(Ps + (wid * 16 + qr) * ST + 2 * qc);
            uint32_t* P1 = (uint32_t*)(Ps + (wid * 16 + qr + 8) * ST + 2 * qc);
            #pragma unroll
            for (int nt = 0; nt < 8; nt++) {
                *(uint2*)(P0 + nt * 8) = make_uint2(f2tf(s[nt][0]), f2tf(s[nt][1]));
                *(uint2*)(P1 + nt * 8) = make_uint2(f2tf(s[nt][2]), f2tf(s[nt][3]));
            }
        }
        __syncwarp();

        // O += P @ V   (A from Ps, B from Vt)
        #pragma unroll
        for (int ks = 0; ks < 8; ks++) {
            const int col = ks * 8 + qc;
            uint32_t ap[4];
            const float* pp = Ps + (wid * 16 + qr) * ST;
            ap[0] = fbits(pp[col]);
            ap[1] = fbits(pp[8 * ST + col]);
            ap[2] = fbits(pp[col + 4]);
            ap[3] = fbits(pp[8 * ST + col + 4]);
            #pragma unroll
            for (int nt = 0; nt < 8; nt++) {
                const float* p = Vt + (nt * 8 + qr) * ST + col;
                mma8(o[nt], ap, fbits(p[0]), fbits(p[4]));
            }
        }
    }

    // Normalize and write O as [B,S,HID]
    const int b = bh >> 4, h = bh & 15;
    const int q = q0 + wid * 16 + qr;
    const float inv0 = 1.f / lr_[0];
    const float inv1 = 1.f / lr_[1];
    float* base0 = g_X + (size_t)(b * SEQ + q) * HID + h * HD;
    float* base1 = g_X + (size_t)(b * SEQ + q + 8) * HID + h * HD;
    #pragma unroll
    for (int nt = 0; nt < 8; nt++) {
        const int col = nt * 8 + 2 * qc;
        *(float2*)(base0 + col) = make_float2(o[nt][0] * inv0, o[nt][1] * inv0);
        *(float2*)(base1 + col) = make_float2(o[nt][2] * inv1, o[nt][3] * inv1);
    }
}

// ---------------------------------------------------------------------------
extern "C" void kernel_launch(void* const* d_in, const int* in_sizes, int n_in,
                              void* d_out, int out_size)
{
    const float* query = (const float*)d_in[0];
    const float* key   = (const float*)d_in[1];
    const float* value = (const float*)d_in[2];
    const float* wq    = (const float*)d_in[3];
    const float* bq    = (const float*)d_in[4];
    const float* wk    = (const float*)d_in[5];
    const float* bk    = (const float*)d_in[6];
    const float* wv    = (const float*)d_in[7];
    const float* bv    = (const float*)d_in[8];
    const float* wf    = (const float*)d_in[9];
    const float* bf    = (const float*)d_in[10];
    float* out = (float*)d_out;

    cudaFuncSetAttribute(gemm_tc, cudaFuncAttributeMaxDynamicSharedMemorySize,
                         GEMM_SMEM);
    cudaFuncSetAttribute(attn_tc, cudaFuncAttributeMaxDynamicSharedMemorySize,
                         ATTN_SMEM);

    dim3 gg(HID / 128, MTOT / 128);   // (8, 64)
    gemm_tc<<<gg, 256, GEMM_SMEM>>>(query, wq, bq, nullptr, 0);
    gemm_tc<<<gg, 256, GEMM_SMEM>>>(key,   wk, bk, nullptr, 1);
    gemm_tc<<<gg, 256, GEMM_SMEM>>>(value, wv, bv, nullptr, 2);

    dim3 ga(SEQ / 64, BATCH * NH);    // (32, 64)
    attn_tc<<<ga, 128, ATTN_SMEM>>>();

    gemm_tc<<<gg, 256, GEMM_SMEM>>>(nullptr, wf, bf, out, 3);
}

// round 4
// speedup vs baseline: 3.3754x; 1.7829x over previous
#include <cuda_runtime.h>
#include <cuda_bf16.h>
#include <cstdint>

#define HID   1024
#define NH    16
#define HD    64
#define BATCH 4
#define SEQ   2048
#define MTOT  (BATCH*SEQ)   // 8192

// Scratch (allocation-free rule: __device__ globals).
__device__ float g_Q[(size_t)MTOT * HID];  // [B,H,S,D]
__device__ float g_K[(size_t)MTOT * HID];  // [B,H,S,D]
__device__ float g_V[(size_t)MTOT * HID];  // [B,H,S,D]
__device__ float g_X[(size_t)MTOT * HID];  // [B,S,HID] attention output

// ---------------------------------------------------------------------------
// tf32 helpers (base-target PTX: works under compute_103)
// ---------------------------------------------------------------------------
static __device__ __forceinline__ uint32_t f2tf(float x) {
    uint32_t r;
    asm("cvt.rna.tf32.f32 %0, %1;" : "=r"(r) : "f"(x));
    return r;
}
// D += A*B  (m16n8k8, tf32 inputs, f32 accum)
static __device__ __forceinline__ void mma8(float* d, const uint32_t* a,
                                            uint32_t b0, uint32_t b1) {
    asm volatile(
        "mma.sync.aligned.m16n8k8.row.col.f32.tf32.tf32.f32 "
        "{%0,%1,%2,%3}, {%4,%5,%6,%7}, {%8,%9}, {%0,%1,%2,%3};"
        : "+f"(d[0]), "+f"(d[1]), "+f"(d[2]), "+f"(d[3])
        : "r"(a[0]), "r"(a[1]), "r"(a[2]), "r"(a[3]), "r"(b0), "r"(b1));
}
static __device__ __forceinline__ uint32_t fbits(float x) { return __float_as_uint(x); }

// ---------------------------------------------------------------------------
// tf32 tensor-core GEMM:  out[m,n] = sum_k X[m,k]*W[n,k] + bias[n]
// CTA 128x128, BK=32, 256 thr (8 warps, 2m x 4n), warp tile 64x32.
// smem stride 36 words => frag pattern (4r+c) mod 32 conflict-free.
// which: 0/1/2 -> scatter into g_Q/g_K/g_V as [B,H,S,D]; 3 -> g_X -> out.
// ---------------------------------------------------------------------------
#define SA 36
#define GEMM_SMEM (2 * 2 * 128 * SA * 4)   // 73728 B

__global__ __launch_bounds__(256) void gemm_tc(const float* __restrict__ X,
                                               const float* __restrict__ W,
                                               const float* __restrict__ bias,
                                               float* __restrict__ out,
                                               int which)
{
    extern __shared__ float sm[];

    const float* Xp = (which == 3) ? g_X : X;
    float* outp = (which == 0) ? g_Q
                : (which == 1) ? g_K
                : (which == 2) ? g_V : out;

    const int tid  = threadIdx.x;
    const int wid  = tid >> 5;
    const int lane = tid & 31;
    const int wm   = wid >> 2;        // 0..1
    const int wn   = wid & 3;         // 0..3
    const int qr   = lane >> 2;       // 0..7
    const int qc   = lane & 3;        // 0..3
    const int m0   = blockIdx.y * 128;
    const int n0   = blockIdx.x * 128;

    const int lr = tid >> 3;          // 0..31
    const int lc = (tid & 7) << 2;    // 0..28
    const float* xg = Xp + (size_t)(m0 + lr) * HID + lc;
    const float* wg = W  + (size_t)(n0 + lr) * HID + lc;

    float4 xa[4], wb[4];
    auto gload = [&](int kc) {
        #pragma unroll
        for (int i = 0; i < 4; i++) {
            const size_t go = (size_t)(i * 32) * HID + kc * 32;
            xa[i] = *(const float4*)(xg + go);
            wb[i] = *(const float4*)(wg + go);
        }
    };
    auto sstore = [&](int buf) {
        float* A = sm + buf * 2 * 128 * SA;
        float* B = A + 128 * SA;
        #pragma unroll
        for (int i = 0; i < 4; i++) {
            const int r = lr + 32 * i;
            *(uint4*)(A + r * SA + lc) =
                make_uint4(f2tf(xa[i].x), f2tf(xa[i].y), f2tf(xa[i].z), f2tf(xa[i].w));
            *(uint4*)(B + r * SA + lc) =
                make_uint4(f2tf(wb[i].x), f2tf(wb[i].y), f2tf(wb[i].z), f2tf(wb[i].w));
        }
    };

    float acc[4][4][4] = {};

    gload(0); sstore(0);
    __syncthreads();

    const int NKC = HID / 32;   // 32
    for (int kc = 0; kc < NKC; kc++) {
        const int cur = kc & 1;
        if (kc + 1 < NKC) gload(kc + 1);

        const float* A = sm + cur * 2 * 128 * SA;
        const float* B = A + 128 * SA;
        #pragma unroll
        for (int ks = 0; ks < 4; ks++) {
            const int col = ks * 8 + qc;
            uint32_t af[4][4], bf[4][2];
            #pragma unroll
            for (int mt = 0; mt < 4; mt++) {
                const float* p = A + (wm * 64 + mt * 16 + qr) * SA + col;
                af[mt][0] = fbits(p[0]);
                af[mt][1] = fbits(p[8 * SA]);
                af[mt][2] = fbits(p[4]);
                af[mt][3] = fbits(p[8 * SA + 4]);
            }
            #pragma unroll
            for (int nt = 0; nt < 4; nt++) {
                const float* p = B + (wn * 32 + nt * 8 + qr) * SA + col;
                bf[nt][0] = fbits(p[0]);
                bf[nt][1] = fbits(p[4]);
            }
            #pragma unroll
            for (int mt = 0; mt < 4; mt++)
                #pragma unroll
                for (int nt = 0; nt < 4; nt++)
                    mma8(acc[mt][nt], af[mt], bf[nt][0], bf[nt][1]);
        }
        if (kc + 1 < NKC) sstore(cur ^ 1);
        __syncthreads();
    }

    // Epilogue
    #pragma unroll
    for (int mt = 0; mt < 4; mt++) {
        const int m = m0 + wm * 64 + mt * 16 + qr;
        #pragma unroll
        for (int nt = 0; nt < 4; nt++) {
            const int n = n0 + wn * 32 + nt * 8 + 2 * qc;
            const float b0 = bias[n], b1 = bias[n + 1];
            float2 v0 = make_float2(acc[mt][nt][0] + b0, acc[mt][nt][1] + b1);
            float2 v1 = make_float2(acc[mt][nt][2] + b0, acc[mt][nt][3] + b1);
            if (which < 3) {
                const int bb = m >> 11, h = n >> 6, d = n & 63;
                const int s0 = m & 2047;
                float* base = outp + ((size_t)(bb * NH + h) * SEQ) * HD + d;
                *(float2*)(base + (size_t)s0 * HD)       = v0;
                *(float2*)(base + (size_t)(s0 + 8) * HD) = v1;
            } else {
                *(float2*)(outp + (size_t)m * HID + n)       = v0;
                *(float2*)(outp + (size_t)(m + 8) * HID + n) = v1;
            }
        }
    }
}

// ---------------------------------------------------------------------------
// Flash attention on mma.sync tf32. Br=Bc=64, head_dim=64.
// 128 threads (4 warps); warp w owns q rows [w*16, w*16+16).
// V kept in NATURAL [kv][d] layout, stride 72 (72 mod 32 == 8) so PV
// B-fragments (b = V[ks*8+qc][nt*8+qr]) are bank-conflict-free and no
// transpose store is needed. Q/K/P use stride 68 (conflict-free for their
// patterns).
// ---------------------------------------------------------------------------
#define ST 68
#define SV 72
#define ATTN_SMEM ((3 * 64 * ST + 64 * SV) * 4)   // 70656 B

__global__ __launch_bounds__(128) void attn_tc()
{
    extern __shared__ float sm[];
    float* Qs = sm;                 // [64][ST]  Q[q][d]
    float* Ks = sm + 64 * ST;       // [64][ST]  K[kv][d]
    float* Ps = sm + 2 * 64 * ST;   // [64][ST]  P[q][kv]
    float* Vs = sm + 3 * 64 * ST;   // [64][SV]  V[kv][d]  (natural)

    const int tid  = threadIdx.x;
    const int wid  = tid >> 5;
    const int lane = tid & 31;
    const int qr   = lane >> 2;
    const int qc   = lane & 3;
    const int q0   = blockIdx.x * 64;
    const int bh   = blockIdx.y;

    const float* Qg = g_Q + (size_t)bh * SEQ * HD;
    const float* Kg = g_K + (size_t)bh * SEQ * HD;
    const float* Vg = g_V + (size_t)bh * SEQ * HD;

    const int r8 = tid >> 4;          // 0..7
    const int c4 = (tid & 15) << 2;   // 0..60

    // Load Q tile (tf32-rounded)
    #pragma unroll
    for (int i = 0; i < 8; i++) {
        const int r = r8 + i * 8;
        float4 v = *(const float4*)(Qg + (size_t)(q0 + r) * HD + c4);
        *(uint4*)(Qs + r * ST + c4) =
            make_uint4(f2tf(v.x), f2tf(v.y), f2tf(v.z), f2tf(v.w));
    }
    __syncthreads();

    // Hoist Q fragments for the whole kernel (A operand of QK^T)
    uint32_t aq[8][4];
    {
        const float* p = Qs + (wid * 16 + qr) * ST;
        #pragma unroll
        for (int ks = 0; ks < 8; ks++) {
            const int col = ks * 8 + qc;
            aq[ks][0] = fbits(p[col]);
            aq[ks][1] = fbits(p[8 * ST + col]);
            aq[ks][2] = fbits(p[col + 4]);
            aq[ks][3] = fbits(p[8 * ST + col + 4]);
        }
    }

    float o[8][4] = {};
    float mr[2] = { -1e30f, -1e30f };
    float lr_[2] = { 0.f, 0.f };
    const float csc = 0.125f * 1.44269504f;  // 1/sqrt(64) * log2(e)

    for (int kt = 0; kt < SEQ; kt += 64) {
        __syncthreads();   // previous tile's reads complete
        #pragma unroll
        for (int i = 0; i < 8; i++) {
            const int r = r8 + i * 8;
            float4 kv = *(const float4*)(Kg + (size_t)(kt + r) * HD + c4);
            *(uint4*)(Ks + r * ST + c4) =
                make_uint4(f2tf(kv.x), f2tf(kv.y), f2tf(kv.z), f2tf(kv.w));
            float4 vv = *(const float4*)(Vg + (size_t)(kt + r) * HD + c4);
            *(uint4*)(Vs + r * SV + c4) =
                make_uint4(f2tf(vv.x), f2tf(vv.y), f2tf(vv.z), f2tf(vv.w));
        }
        __syncthreads();

        // S = Q @ K^T  -> s[nt][4] per thread  (nt outer: pointer hoisted)
        float s[8][4] = {};
        #pragma unroll
        for (int nt = 0; nt < 8; nt++) {
            const float* pb = Ks + (nt * 8 + qr) * ST + qc;
            #pragma unroll
            for (int ks = 0; ks < 8; ks++)
                mma8(s[nt], aq[ks], fbits(pb[ks * 8]), fbits(pb[ks * 8 + 4]));
        }

        // Online softmax (rows qr and qr+8 of this warp's 16-row block)
        float tmax0 = -1e30f, tmax1 = -1e30f;
        #pragma unroll
        for (int nt = 0; nt < 8; nt++) {
            s[nt][0] *= csc; s[nt][1] *= csc; s[nt][2] *= csc; s[nt][3] *= csc;
            tmax0 = fmaxf(tmax0, fmaxf(s[nt][0], s[nt][1]));
            tmax1 = fmaxf(tmax1, fmaxf(s[nt][2], s[nt][3]));
        }
        tmax0 = fmaxf(tmax0, __shfl_xor_sync(0xffffffffu, tmax0, 1));
        tmax0 = fmaxf(tmax0, __shfl_xor_sync(0xffffffffu, tmax0, 2));
        tmax1 = fmaxf(tmax1, __shfl_xor_sync(0xffffffffu, tmax1, 1));
        tmax1 = fmaxf(tmax1, __shfl_xor_sync(0xffffffffu, tmax1, 2));
        const float mn0 = fmaxf(mr[0], tmax0);
        const float mn1 = fmaxf(mr[1], tmax1);
        const float corr0 = exp2f(mr[0] - mn0);
        const float corr1 = exp2f(mr[1] - mn1);
        mr[0] = mn0; mr[1] = mn1;

        float rs0 = 0.f, rs1 = 0.f;
        #pragma unroll
        for (int nt = 0; nt < 8; nt++) {
            s[nt][0] = exp2f(s[nt][0] - mn0);
            s[nt][1] = exp2f(s[nt][1] - mn0);
            s[nt][2] = exp2f(s[nt][2] - mn1);
            s[nt][3] = exp2f(s[nt][3] - mn1);
            rs0 += s[nt][0] + s[nt][1];
            rs1 += s[nt][2] + s[nt][3];
        }
        rs0 += __shfl_xor_sync(0xffffffffu, rs0, 1);
        rs0 += __shfl_xor_sync(0xffffffffu, rs0, 2);
        rs1 += __shfl_xor_sync(0xffffffffu, rs1, 1);
        rs1 += __shfl_xor_sync(0xffffffffu, rs1, 2);
        lr_[0] = lr_[0] * corr0 + rs0;
        lr_[1] = lr_[1] * corr1 + rs1;

        #pragma unroll
        for (int nt = 0; nt < 8; nt++) {
            o[nt][0] *= corr0; o[nt][1] *= corr0;
            o[nt][2] *= corr1; o[nt][3] *= corr1;
        }

        // Store P (tf32-rounded) into this warp's rows of Ps
        {
            uint32_t* P0 = (uint32_t*)(Ps + (wid * 16 + qr) * ST + 2 * qc);
            uint32_t* P1 = (uint32_t*)(Ps + (wid * 16 + qr + 8) * ST + 2 * qc);
            #pragma unroll
            for (int nt = 0; nt < 8; nt++) {
                *(uint2*)(P0 + nt * 8) = make_uint2(f2tf(s[nt][0]), f2tf(s[nt][1]));
                *(uint2*)(P1 + nt * 8) = make_uint2(f2tf(s[nt][2]), f2tf(s[nt][3]));
            }
        }
        __syncwarp();

        // O += P @ V   (A from Ps; B straight from natural-layout Vs)
        #pragma unroll
        for (int ks = 0; ks < 8; ks++) {
            const int col = ks * 8 + qc;
            uint32_t ap[4];
            const float* pp = Ps + (wid * 16 + qr) * ST;
            ap[0] = fbits(pp[col]);
            ap[1] = fbits(pp[8 * ST + col]);
            ap[2] = fbits(pp[col + 4]);
            ap[3] = fbits(pp[8 * ST + col + 4]);
            const float* pv = Vs + col * SV + qr;   // V[ks*8+qc][nt*8+qr]
            #pragma unroll
            for (int nt = 0; nt < 8; nt++)
                mma8(o[nt], ap, fbits(pv[nt * 8]), fbits(pv[nt * 8 + 4 * SV]));
        }
    }

    // Normalize and write O as [B,S,HID]
    const int b = bh >> 4, h = bh & 15;
    const int q = q0 + wid * 16 + qr;
    const float inv0 = 1.f / lr_[0];
    const float inv1 = 1.f / lr_[1];
    float* base0 = g_X + (size_t)(b * SEQ + q) * HID + h * HD;
    float* base1 = g_X + (size_t)(b * SEQ + q + 8) * HID + h * HD;
    #pragma unroll
    for (int nt = 0; nt < 8; nt++) {
        const int col = nt * 8 + 2 * qc;
        *(float2*)(base0 + col) = make_float2(o[nt][0] * inv0, o[nt][1] * inv0);
        *(float2*)(base1 + col) = make_float2(o[nt][2] * inv1, o[nt][3] * inv1);
    }
}

// ---------------------------------------------------------------------------
extern "C" void kernel_launch(void* const* d_in, const int* in_sizes, int n_in,
                              void* d_out, int out_size)
{
    const float* query = (const float*)d_in[0];
    const float* key   = (const float*)d_in[1];
    const float* value = (const float*)d_in[2];
    const float* wq    = (const float*)d_in[3];
    const float* bq    = (const float*)d_in[4];
    const float* wk    = (const float*)d_in[5];
    const float* bk    = (const float*)d_in[6];
    const float* wv    = (const float*)d_in[7];
    const float* bv    = (const float*)d_in[8];
    const float* wf    = (const float*)d_in[9];
    const float* bf    = (const float*)d_in[10];
    float* out = (float*)d_out;

    cudaFuncSetAttribute(gemm_tc, cudaFuncAttributeMaxDynamicSharedMemorySize,
                         GEMM_SMEM);
    cudaFuncSetAttribute(attn_tc, cudaFuncAttributeMaxDynamicSharedMemorySize,
                         ATTN_SMEM);

    dim3 gg(HID / 128, MTOT / 128);   // (8, 64)
    gemm_tc<<<gg, 256, GEMM_SMEM>>>(query, wq, bq, nullptr, 0);
    gemm_tc<<<gg, 256, GEMM_SMEM>>>(key,   wk, bk, nullptr, 1);
    gemm_tc<<<gg, 256, GEMM_SMEM>>>(value, wv, bv, nullptr, 2);

    dim3 ga(SEQ / 64, BATCH * NH);    // (32, 64)
    attn_tc<<<ga, 128, ATTN_SMEM>>>();

    gemm_tc<<<gg, 256, GEMM_SMEM>>>(nullptr, wf, bf, out, 3);
}

// round 5
// speedup vs baseline: 3.8832x; 1.1505x over previous
#include <cuda_runtime.h>
#include <cuda_bf16.h>
#include <cstdint>

#define HID   1024
#define NH    16
#define HD    64
#define BATCH 4
#define SEQ   2048
#define MTOT  (BATCH*SEQ)   // 8192

// Scratch (allocation-free rule: __device__ globals).
__device__ __align__(16) float g_Q[(size_t)MTOT * HID];  // [B,H,S,D]
__device__ __align__(16) float g_K[(size_t)MTOT * HID];  // [B,H,S,D]
__device__ __align__(16) float g_V[(size_t)MTOT * HID];  // [B,H,S,D]
__device__ __align__(16) float g_X[(size_t)MTOT * HID];  // [B,S,HID]

// ---------------------------------------------------------------------------
// tf32 helpers (base-target PTX: works under compute_103)
// ---------------------------------------------------------------------------
static __device__ __forceinline__ uint32_t f2tf(float x) {
    uint32_t r;
    asm("cvt.rna.tf32.f32 %0, %1;" : "=r"(r) : "f"(x));
    return r;
}
// D += A*B  (m16n8k8, tf32 inputs, f32 accum)
static __device__ __forceinline__ void mma8(float* d, const uint32_t* a,
                                            uint32_t b0, uint32_t b1) {
    asm volatile(
        "mma.sync.aligned.m16n8k8.row.col.f32.tf32.tf32.f32 "
        "{%0,%1,%2,%3}, {%4,%5,%6,%7}, {%8,%9}, {%0,%1,%2,%3};"
        : "+f"(d[0]), "+f"(d[1]), "+f"(d[2]), "+f"(d[3])
        : "r"(a[0]), "r"(a[1]), "r"(a[2]), "r"(a[3]), "r"(b0), "r"(b1));
}
static __device__ __forceinline__ uint32_t fbits(float x) { return __float_as_uint(x); }
static __device__ __forceinline__ uint32_t smem_u32(const void* p) {
    uint32_t a;
    asm("{ .reg .u64 t; cvta.to.shared.u64 t, %1; cvt.u32.u64 %0, t; }"
        : "=r"(a) : "l"(p));
    return a;
}
#define CP16(dst, src) \
    asm volatile("cp.async.cg.shared.global [%0], [%1], 16;" :: "r"(dst), "l"(src) : "memory")

// ---------------------------------------------------------------------------
// tf32 GEMM:  out[m,n] = sum_k X[m,k]*W[n,k] + bias[n]
// CTA 128x128, BK=32, 128 threads = 4 warps (2x2), warp tile 64x64.
// 3-stage cp.async pipeline; raw fp32 staged in smem, cvt.rna at frag load.
// smem row stride 36 words -> all frag patterns bank-conflict-free.
// mode 0: blockIdx.z = which in {0,1,2} -> scatter to g_Q/g_K/g_V [B,H,S,D]
// mode 1: X = g_X, W/bias from slot 0 args, plain row-major store to out.
// ---------------------------------------------------------------------------
#define GSA   36
#define STGW  (2 * 128 * GSA)                 // words per stage (A then B)
#define GEMM_SMEM (3 * STGW * 4)              // 110592 B

__global__ __launch_bounds__(128, 2) void gemm_tc(
    const float* __restrict__ Xq, const float* __restrict__ Xk,
    const float* __restrict__ Xv,
    const float* __restrict__ Wq, const float* __restrict__ Wk,
    const float* __restrict__ Wv,
    const float* __restrict__ Bq, const float* __restrict__ Bk,
    const float* __restrict__ Bv,
    float* __restrict__ outFinal, int mode)
{
    extern __shared__ float sm[];
    const uint32_t sbase = smem_u32(sm);

    const int which = (mode == 0) ? (int)blockIdx.z : 3;
    const float* Xp; const float* W; const float* bias; float* outp;
    if (which == 0)      { Xp = Xq;  W = Wq; bias = Bq; outp = g_Q; }
    else if (which == 1) { Xp = Xk;  W = Wk; bias = Bk; outp = g_K; }
    else if (which == 2) { Xp = Xv;  W = Wv; bias = Bv; outp = g_V; }
    else                 { Xp = g_X; W = Wq; bias = Bq; outp = outFinal; }

    const int tid  = threadIdx.x;
    const int wid  = tid >> 5;
    const int lane = tid & 31;
    const int wm   = wid >> 1;        // 0..1
    const int wn   = wid & 1;         // 0..1
    const int qr   = lane >> 2;       // 0..7
    const int qc   = lane & 3;        // 0..3
    const int m0   = blockIdx.y * 128;
    const int n0   = blockIdx.x * 128;

    // Async copy of one K-chunk (A tile 128x32 + B tile 128x32, raw fp32).
    auto issue = [&](int kc) {
        const int st = kc % 3;
        const uint32_t sA = sbase + st * STGW * 4;
        const uint32_t sB = sA + 128 * GSA * 4;
        #pragma unroll
        for (int c = 0; c < 8; c++) {
            const int g   = c * 128 + tid;
            const int row = g >> 3;
            const int cw  = (g & 7) << 2;
            const uint32_t off = (uint32_t)(row * GSA + cw) * 4;
            CP16(sA + off, Xp + (size_t)(m0 + row) * HID + kc * 32 + cw);
            CP16(sB + off, W  + (size_t)(n0 + row) * HID + kc * 32 + cw);
        }
        asm volatile("cp.async.commit_group;" ::: "memory");
    };

    float acc[4][8][4] = {};

    issue(0);
    issue(1);

    const int NKC = HID / 32;   // 32
    for (int kc = 0; kc < NKC; kc++) {
        if (kc + 2 < NKC) {
            issue(kc + 2);
            asm volatile("cp.async.wait_group 2;" ::: "memory");
        } else if (kc + 1 < NKC) {
            asm volatile("cp.async.wait_group 1;" ::: "memory");
        } else {
            asm volatile("cp.async.wait_group 0;" ::: "memory");
        }
        __syncthreads();

        const float* A = sm + (kc % 3) * STGW;
        const float* B = A + 128 * GSA;
        #pragma unroll
        for (int ks = 0; ks < 4; ks++) {
            const int col = ks * 8 + qc;
            uint32_t af[4][4], bf[8][2];
            #pragma unroll
            for (int mt = 0; mt < 4; mt++) {
                const float* p = A + (wm * 64 + mt * 16 + qr) * GSA + col;
                af[mt][0] = f2tf(p[0]);
                af[mt][1] = f2tf(p[8 * GSA]);
                af[mt][2] = f2tf(p[4]);
                af[mt][3] = f2tf(p[8 * GSA + 4]);
            }
            #pragma unroll
            for (int nt = 0; nt < 8; nt++) {
                const float* p = B + (wn * 64 + nt * 8 + qr) * GSA + col;
                bf[nt][0] = f2tf(p[0]);
                bf[nt][1] = f2tf(p[4]);
            }
            #pragma unroll
            for (int mt = 0; mt < 4; mt++)
                #pragma unroll
                for (int nt = 0; nt < 8; nt++)
                    mma8(acc[mt][nt], af[mt], bf[nt][0], bf[nt][1]);
        }
        __syncthreads();   // stage (kc%3) free for reuse at kc+1's issue
    }

    // Epilogue
    #pragma unroll
    for (int mt = 0; mt < 4; mt++) {
        const int m = m0 + wm * 64 + mt * 16 + qr;
        #pragma unroll
        for (int nt = 0; nt < 8; nt++) {
            const int n = n0 + wn * 64 + nt * 8 + 2 * qc;
            const float b0 = bias[n], b1 = bias[n + 1];
            float2 v0 = make_float2(acc[mt][nt][0] + b0, acc[mt][nt][1] + b1);
            float2 v1 = make_float2(acc[mt][nt][2] + b0, acc[mt][nt][3] + b1);
            if (which < 3) {
                const int bb = m >> 11, h = n >> 6, d = n & 63;
                const int s0 = m & 2047;
                float* base = outp + ((size_t)(bb * NH + h) * SEQ) * HD + d;
                *(float2*)(base + (size_t)s0 * HD)       = v0;
                *(float2*)(base + (size_t)(s0 + 8) * HD) = v1;
            } else {
                *(float2*)(outp + (size_t)m * HID + n)       = v0;
                *(float2*)(outp + (size_t)(m + 8) * HID + n) = v1;
            }
        }
    }
}

// ---------------------------------------------------------------------------
// Flash attention on mma.sync tf32. Br=Bc=64, head_dim=64, 4 warps.
// Ps OVERLAYS Qs (Q only needed for the pre-loop fragment hoist), cutting
// smem to 53248 B -> 4 CTAs/SM. V in natural [kv][d] layout, stride 72.
// ---------------------------------------------------------------------------
#define ST 68
#define SV 72
#define ATTN_SMEM ((2 * 64 * ST + 64 * SV) * 4)   // 53248 B

__global__ __launch_bounds__(128, 4) void attn_tc()
{
    extern __shared__ float sm[];
    float* Qs = sm;                 // [64][ST]  Q[q][d]   (dead after hoist)
    float* Ks = sm + 64 * ST;       // [64][ST]  K[kv][d]
    float* Vs = sm + 2 * 64 * ST;   // [64][SV]  V[kv][d]  (natural)
    float* Ps = Qs;                 // [64][ST]  P[q][kv]  (overlay)

    const int tid  = threadIdx.x;
    const int wid  = tid >> 5;
    const int lane = tid & 31;
    const int qr   = lane >> 2;
    const int qc   = lane & 3;
    const int q0   = blockIdx.x * 64;
    const int bh   = blockIdx.y;

    const float* Qg = g_Q + (size_t)bh * SEQ * HD;
    const float* Kg = g_K + (size_t)bh * SEQ * HD;
    const float* Vg = g_V + (size_t)bh * SEQ * HD;

    const int r8 = tid >> 4;          // 0..7
    const int c4 = (tid & 15) << 2;   // 0..60

    // Load Q tile (tf32-rounded)
    #pragma unroll
    for (int i = 0; i < 8; i++) {
        const int r = r8 + i * 8;
        float4 v = *(const float4*)(Qg + (size_t)(q0 + r) * HD + c4);
        *(uint4*)(Qs + r * ST + c4) =
            make_uint4(f2tf(v.x), f2tf(v.y), f2tf(v.z), f2tf(v.w));
    }
    __syncthreads();

    // Hoist Q fragments for the whole kernel (A operand of QK^T)
    uint32_t aq[8][4];
    {
        const float* p = Qs + (wid * 16 + qr) * ST;
        #pragma unroll
        for (int ks = 0; ks < 8; ks++) {
            const int col = ks * 8 + qc;
            aq[ks][0] = fbits(p[col]);
            aq[ks][1] = fbits(p[8 * ST + col]);
            aq[ks][2] = fbits(p[col + 4]);
            aq[ks][3] = fbits(p[8 * ST + col + 4]);
        }
    }

    float o[8][4] = {};
    float mr[2] = { -1e30f, -1e30f };
    float lr_[2] = { 0.f, 0.f };
    const float csc = 0.125f * 1.44269504f;  // 1/sqrt(64) * log2(e)

    for (int kt = 0; kt < SEQ; kt += 64) {
        __syncthreads();   // previous tile's reads complete (incl. Q hoist @kt=0)
        #pragma unroll
        for (int i = 0; i < 8; i++) {
            const int r = r8 + i * 8;
            float4 kv = *(const float4*)(Kg + (size_t)(kt + r) * HD + c4);
            *(uint4*)(Ks + r * ST + c4) =
                make_uint4(f2tf(kv.x), f2tf(kv.y), f2tf(kv.z), f2tf(kv.w));
            float4 vv = *(const float4*)(Vg + (size_t)(kt + r) * HD + c4);
            *(uint4*)(Vs + r * SV + c4) =
                make_uint4(f2tf(vv.x), f2tf(vv.y), f2tf(vv.z), f2tf(vv.w));
        }
        __syncthreads();

        // S = Q @ K^T
        float s[8][4] = {};
        #pragma unroll
        for (int nt = 0; nt < 8; nt++) {
            const float* pb = Ks + (nt * 8 + qr) * ST + qc;
            #pragma unroll
            for (int ks = 0; ks < 8; ks++)
                mma8(s[nt], aq[ks], fbits(pb[ks * 8]), fbits(pb[ks * 8 + 4]));
        }

        // Online softmax (rows qr and qr+8 of this warp's 16-row block)
        float tmax0 = -1e30f, tmax1 = -1e30f;
        #pragma unroll
        for (int nt = 0; nt < 8; nt++) {
            s[nt][0] *= csc; s[nt][1] *= csc; s[nt][2] *= csc; s[nt][3] *= csc;
            tmax0 = fmaxf(tmax0, fmaxf(s[nt][0], s[nt][1]));
            tmax1 = fmaxf(tmax1, fmaxf(s[nt][2], s[nt][3]));
        }
        tmax0 = fmaxf(tmax0, __shfl_xor_sync(0xffffffffu, tmax0, 1));
        tmax0 = fmaxf(tmax0, __shfl_xor_sync(0xffffffffu, tmax0, 2));
        tmax1 = fmaxf(tmax1, __shfl_xor_sync(0xffffffffu, tmax1, 1));
        tmax1 = fmaxf(tmax1, __shfl_xor_sync(0xffffffffu, tmax1, 2));
        const float mn0 = fmaxf(mr[0], tmax0);
        const float mn1 = fmaxf(mr[1], tmax1);
        const float corr0 = exp2f(mr[0] - mn0);
        const float corr1 = exp2f(mr[1] - mn1);
        mr[0] = mn0; mr[1] = mn1;

        float rs0 = 0.f, rs1 = 0.f;
        #pragma unroll
        for (int nt = 0; nt < 8; nt++) {
            s[nt][0] = exp2f(s[nt][0] - mn0);
            s[nt][1] = exp2f(s[nt][1] - mn0);
            s[nt][2] = exp2f(s[nt][2] - mn1);
            s[nt][3] = exp2f(s[nt][3] - mn1);
            rs0 += s[nt][0] + s[nt][1];
            rs1 += s[nt][2] + s[nt][3];
        }
        rs0 += __shfl_xor_sync(0xffffffffu, rs0, 1);
        rs0 += __shfl_xor_sync(0xffffffffu, rs0, 2);
        rs1 += __shfl_xor_sync(0xffffffffu, rs1, 1);
        rs1 += __shfl_xor_sync(0xffffffffu, rs1, 2);
        lr_[0] = lr_[0] * corr0 + rs0;
        lr_[1] = lr_[1] * corr1 + rs1;

        #pragma unroll
        for (int nt = 0; nt < 8; nt++) {
            o[nt][0] *= corr0; o[nt][1] *= corr0;
            o[nt][2] *= corr1; o[nt][3] *= corr1;
        }

        // Store P (tf32-rounded) into this warp's own 16 rows of Ps
        {
            uint32_t* P0 = (uint32_t*)(Ps + (wid * 16 + qr) * ST + 2 * qc);
            uint32_t* P1 = (uint32_t*)(Ps + (wid * 16 + qr + 8) * ST + 2 * qc);
            #pragma unroll
            for (int nt = 0; nt < 8; nt++) {
                *(uint2*)(P0 + nt * 8) = make_uint2(f2tf(s[nt][0]), f2tf(s[nt][1]));
                *(uint2*)(P1 + nt * 8) = make_uint2(f2tf(s[nt][2]), f2tf(s[nt][3]));
            }
        }
        __syncwarp();

        // O += P @ V   (A from own rows of Ps; B from natural-layout Vs)
        #pragma unroll
        for (int ks = 0; ks < 8; ks++) {
            const int col = ks * 8 + qc;
            uint32_t ap[4];
            const float* pp = Ps + (wid * 16 + qr) * ST;
            ap[0] = fbits(pp[col]);
            ap[1] = fbits(pp[8 * ST + col]);
            ap[2] = fbits(pp[col + 4]);
            ap[3] = fbits(pp[8 * ST + col + 4]);
            const float* pv = Vs + col * SV + qr;   // V[ks*8+qc][nt*8+qr]
            #pragma unroll
            for (int nt = 0; nt < 8; nt++)
                mma8(o[nt], ap, fbits(pv[nt * 8]), fbits(pv[nt * 8 + 4 * SV]));
        }
    }

    // Normalize and write O as [B,S,HID]
    const int b = bh >> 4, h = bh & 15;
    const int q = q0 + wid * 16 + qr;
    const float inv0 = 1.f / lr_[0];
    const float inv1 = 1.f / lr_[1];
    float* base0 = g_X + (size_t)(b * SEQ + q) * HID + h * HD;
    float* base1 = g_X + (size_t)(b * SEQ + q + 8) * HID + h * HD;
    #pragma unroll
    for (int nt = 0; nt < 8; nt++) {
        const int col = nt * 8 + 2 * qc;
        *(float2*)(base0 + col) = make_float2(o[nt][0] * inv0, o[nt][1] * inv0);
        *(float2*)(base1 + col) = make_float2(o[nt][2] * inv1, o[nt][3] * inv1);
    }
}

// ---------------------------------------------------------------------------
extern "C" void kernel_launch(void* const* d_in, const int* in_sizes, int n_in,
                              void* d_out, int out_size)
{
    const float* query = (const float*)d_in[0];
    const float* key   = (const float*)d_in[1];
    const float* value = (const float*)d_in[2];
    const float* wq    = (const float*)d_in[3];
    const float* bq    = (const float*)d_in[4];
    const float* wk    = (const float*)d_in[5];
    const float* bk    = (const float*)d_in[6];
    const float* wv    = (const float*)d_in[7];
    const float* bv    = (const float*)d_in[8];
    const float* wf    = (const float*)d_in[9];
    const float* bf    = (const float*)d_in[10];
    float* out = (float*)d_out;

    cudaFuncSetAttribute(gemm_tc, cudaFuncAttributeMaxDynamicSharedMemorySize,
                         GEMM_SMEM);
    cudaFuncSetAttribute(attn_tc, cudaFuncAttributeMaxDynamicSharedMemorySize,
                         ATTN_SMEM);

    // Q,K,V projections merged into one launch (blockIdx.z = which)
    dim3 gq(HID / 128, MTOT / 128, 3);   // (8, 64, 3)
    gemm_tc<<<gq, 128, GEMM_SMEM>>>(query, key, value, wq, wk, wv,
                                    bq, bk, bv, nullptr, 0);

    dim3 ga(SEQ / 64, BATCH * NH);       // (32, 64)
    attn_tc<<<ga, 128, ATTN_SMEM>>>();

    // Final projection: X = g_X, W/bias passed in slot 0
    dim3 gf(HID / 128, MTOT / 128, 1);
    gemm_tc<<<gf, 128, GEMM_SMEM>>>(nullptr, nullptr, nullptr, wf, nullptr,
                                    nullptr, bf, nullptr, nullptr, out, 1);
}

// round 6
// speedup vs baseline: 6.6619x; 1.7156x over previous
#include <cuda_runtime.h>
#include <cuda_fp16.h>
#include <cstdint>

#define HID   1024
#define NH    16
#define HD    64
#define BATCH 4
#define SEQ   2048
#define MTOT  (BATCH*SEQ)   // 8192

// Scratch (allocation-free rule: __device__ globals). All fp16.
__device__ __align__(16) __half h_Xq[(size_t)MTOT * HID];
__device__ __align__(16) __half h_Xk[(size_t)MTOT * HID];
__device__ __align__(16) __half h_Xv[(size_t)MTOT * HID];
__device__ __align__(16) __half h_Wq[(size_t)HID * HID];
__device__ __align__(16) __half h_Wk[(size_t)HID * HID];
__device__ __align__(16) __half h_Wv[(size_t)HID * HID];
__device__ __align__(16) __half h_Wf[(size_t)HID * HID];
__device__ __align__(16) __half g_Qh[(size_t)MTOT * HID];   // [B,H,S,D]
__device__ __align__(16) __half g_Kh[(size_t)MTOT * HID];   // [B,H,S,D]
__device__ __align__(16) __half g_Vt[(size_t)MTOT * HID];   // [B,H,D,S]  (transposed!)
__device__ __align__(16) __half g_Xh[(size_t)MTOT * HID];   // [B,S,HID]

// ---------------------------------------------------------------------------
static __device__ __forceinline__ uint32_t smem_u32(const void* p) {
    uint32_t a;
    asm("{ .reg .u64 t; cvta.to.shared.u64 t, %1; cvt.u32.u64 %0, t; }"
        : "=r"(a) : "l"(p));
    return a;
}
// D += A*B  (m16n8k16, f16 inputs, f32 accum) — base-target sm_80 feature
static __device__ __forceinline__ void mma16(float* d, const uint32_t* a,
                                             uint32_t b0, uint32_t b1) {
    asm volatile(
        "mma.sync.aligned.m16n8k16.row.col.f32.f16.f16.f32 "
        "{%0,%1,%2,%3}, {%4,%5,%6,%7}, {%8,%9}, {%0,%1,%2,%3};"
        : "+f"(d[0]), "+f"(d[1]), "+f"(d[2]), "+f"(d[3])
        : "r"(a[0]), "r"(a[1]), "r"(a[2]), "r"(a[3]), "r"(b0), "r"(b1));
}
static __device__ __forceinline__ uint32_t packh2(float x, float y) {
    __half2 h = __floats2half2_rn(x, y);
    return *(uint32_t*)&h;
}
#define CP16(dst, src) \
    asm volatile("cp.async.cg.shared.global [%0], [%1], 16;" :: "r"(dst), "l"(src) : "memory")
#define CP_COMMIT() asm volatile("cp.async.commit_group;" ::: "memory")
#define CP_WAIT1()  asm volatile("cp.async.wait_group 1;" ::: "memory")
#define CP_WAIT0()  asm volatile("cp.async.wait_group 0;" ::: "memory")

// ---------------------------------------------------------------------------
// fp32 -> fp16 convert: 3 X inputs + 4 weights, vectorized float4 -> half2x2.
// ---------------------------------------------------------------------------
#define N4X (MTOT * HID / 4)   // 2097152
#define N4W (HID * HID / 4)    // 262144
#define N4TOT (3 * N4X + 4 * N4W)

__global__ __launch_bounds__(256) void cvt_h(
    const float* __restrict__ q, const float* __restrict__ k,
    const float* __restrict__ v,
    const float* __restrict__ wq, const float* __restrict__ wk,
    const float* __restrict__ wv, const float* __restrict__ wf)
{
    const int id = blockIdx.x * 256 + threadIdx.x;
    if (id >= N4TOT) return;
    const float* src; __half* dst; int off;
    if (id < N4X)              { src = q;  dst = h_Xq; off = id; }
    else if (id < 2 * N4X)     { src = k;  dst = h_Xk; off = id - N4X; }
    else if (id < 3 * N4X)     { src = v;  dst = h_Xv; off = id - 2 * N4X; }
    else {
        int w = id - 3 * N4X;
        if (w < N4W)           { src = wq; dst = h_Wq; off = w; }
        else if (w < 2 * N4W)  { src = wk; dst = h_Wk; off = w - N4W; }
        else if (w < 3 * N4W)  { src = wv; dst = h_Wv; off = w - 2 * N4W; }
        else                   { src = wf; dst = h_Wf; off = w - 3 * N4W; }
    }
    float4 x = *(const float4*)(src + (size_t)off * 4);
    uint2 o;
    o.x = packh2(x.x, x.y);
    o.y = packh2(x.z, x.w);
    *(uint2*)(dst + (size_t)off * 4) = o;
}

// ---------------------------------------------------------------------------
// fp16 GEMM:  out[m,n] = sum_k X[m,k]*W[n,k] + bias[n]  (fp32 accum)
// CTA 128x128, BK=64, 128 thr (4 warps 2x2), warp tile 64x64.
// 3-stage cp.async pipeline on half data, 1 barrier per K-iter.
// smem row: 64 halves + 8 pad = 144 B (36 words, ≡4 mod 32 → conflict-free).
// mode 0: blockIdx.z=which {0,1,2}: Q,K -> [B,H,S,D] half; V -> [B,H,D,S].
// mode 1: X=g_Xh, W=h_Wf, fp32 row-major store to out.
// ---------------------------------------------------------------------------
#define GROW  144                         // bytes per smem row
#define GSTG  (2 * 128 * GROW)            // 36864 B per stage (A then B)
#define GEMM_SMEM (3 * GSTG)              // 110592 B

__global__ __launch_bounds__(128, 2) void gemm_h(
    const float* __restrict__ Bq, const float* __restrict__ Bk,
    const float* __restrict__ Bv, float* __restrict__ outFinal, int mode)
{
    extern __shared__ char smc[];
    const uint32_t sbase = smem_u32(smc);

    const int which = (mode == 0) ? (int)blockIdx.z : 3;
    const __half* Xp; const __half* W; const float* bias;
    if (which == 0)      { Xp = h_Xq; W = h_Wq; bias = Bq; }
    else if (which == 1) { Xp = h_Xk; W = h_Wk; bias = Bk; }
    else if (which == 2) { Xp = h_Xv; W = h_Wv; bias = Bv; }
    else                 { Xp = g_Xh; W = h_Wf; bias = Bq; }

    const int tid  = threadIdx.x;
    const int wid  = tid >> 5;
    const int lane = tid & 31;
    const int wm   = wid >> 1;
    const int wn   = wid & 1;
    const int qr   = lane >> 2;
    const int qc   = lane & 3;
    const int m0   = blockIdx.y * 128;
    const int n0   = blockIdx.x * 128;

    // cp.async one K-chunk: A 128x64h + B 128x64h
    auto issue = [&](int kc) {
        const uint32_t sA = sbase + (kc % 3) * GSTG;
        const uint32_t sB = sA + 128 * GROW;
        #pragma unroll
        for (int c = 0; c < 8; c++) {
            const int g   = c * 128 + tid;
            const int row = g >> 3;
            const int seg = g & 7;
            const uint32_t off = (uint32_t)row * GROW + seg * 16;
            CP16(sA + off, Xp + (size_t)(m0 + row) * HID + kc * 64 + seg * 8);
            CP16(sB + off, W  + (size_t)(n0 + row) * HID + kc * 64 + seg * 8);
        }
        CP_COMMIT();
    };

    float acc[4][8][4] = {};

    issue(0);
    issue(1);

    const int NKC = HID / 64;   // 16
    for (int kc = 0; kc < NKC; kc++) {
        if (kc + 1 < NKC) CP_WAIT1(); else CP_WAIT0();
        __syncthreads();
        if (kc + 2 < NKC) issue(kc + 2);

        const uint32_t* A2 = (const uint32_t*)(smc + (kc % 3) * GSTG);
        const uint32_t* B2 = A2 + 128 * (GROW / 4);
        #pragma unroll
        for (int ks = 0; ks < 4; ks++) {
            const int c2 = ks * 8 + qc;
            uint32_t af[4][4], bf[8][2];
            #pragma unroll
            for (int mt = 0; mt < 4; mt++) {
                const int r = wm * 64 + mt * 16 + qr;
                af[mt][0] = A2[r * 36 + c2];
                af[mt][1] = A2[(r + 8) * 36 + c2];
                af[mt][2] = A2[r * 36 + c2 + 4];
                af[mt][3] = A2[(r + 8) * 36 + c2 + 4];
            }
            #pragma unroll
            for (int nt = 0; nt < 8; nt++) {
                const int r = wn * 64 + nt * 8 + qr;
                bf[nt][0] = B2[r * 36 + c2];
                bf[nt][1] = B2[r * 36 + c2 + 4];
            }
            #pragma unroll
            for (int mt = 0; mt < 4; mt++)
                #pragma unroll
                for (int nt = 0; nt < 8; nt++)
                    mma16(acc[mt][nt], af[mt], bf[nt][0], bf[nt][1]);
        }
    }
    // (no trailing barrier needed: epilogue only reads registers)

    // Epilogue
    #pragma unroll
    for (int mt = 0; mt < 4; mt++) {
        const int m = m0 + wm * 64 + mt * 16 + qr;
        #pragma unroll
        for (int nt = 0; nt < 8; nt++) {
            const int n = n0 + wn * 64 + nt * 8 + 2 * qc;
            const float b0 = bias[n], b1 = bias[n + 1];
            const float v00 = acc[mt][nt][0] + b0, v01 = acc[mt][nt][1] + b1;
            const float v10 = acc[mt][nt][2] + b0, v11 = acc[mt][nt][3] + b1;
            if (which == 3) {
                *(float2*)(outFinal + (size_t)m * HID + n)       = make_float2(v00, v01);
                *(float2*)(outFinal + (size_t)(m + 8) * HID + n) = make_float2(v10, v11);
            } else {
                const int bb = m >> 11, s = m & 2047;
                const int h = n >> 6,  d = n & 63;
                if (which == 2) {
                    // V: transposed store [B,H,D,S]
                    __half* base = g_Vt + ((size_t)(bb * NH + h) * HD) * SEQ;
                    base[(size_t)(d + 0) * SEQ + s]     = __float2half(v00);
                    base[(size_t)(d + 1) * SEQ + s]     = __float2half(v01);
                    base[(size_t)(d + 0) * SEQ + s + 8] = __float2half(v10);
                    base[(size_t)(d + 1) * SEQ + s + 8] = __float2half(v11);
                } else {
                    __half* outh = (which == 0) ? g_Qh : g_Kh;
                    __half* base = outh + ((size_t)(bb * NH + h) * SEQ) * HD + d;
                    *(uint32_t*)(base + (size_t)s * HD)       = packh2(v00, v01);
                    *(uint32_t*)(base + (size_t)(s + 8) * HD) = packh2(v10, v11);
                }
            }
        }
    }
}

// ---------------------------------------------------------------------------
// fp16 flash attention. Br=Bc=64, head_dim=64, 4 warps (warp = 16 q rows).
// K natural [kv][d], V pre-transposed [d][kv] (both cp.async double-buffered).
// P never touches smem: S C-fragments repack directly into PV A-fragments.
// smem rows: 64 halves + 8 pad = 144 B. Total 46080 B -> 4 CTAs/SM.
// ---------------------------------------------------------------------------
#define AQ_OFF 0
#define AK_OFF(st) (9216 + (st) * 9216)
#define AV_OFF(st) (27648 + (st) * 9216)
#define ATTN_SMEM 46080

__global__ __launch_bounds__(128, 4) void attn_h()
{
    extern __shared__ char smc[];
    const uint32_t sbase = smem_u32(smc);

    const int tid  = threadIdx.x;
    const int wid  = tid >> 5;
    const int lane = tid & 31;
    const int qr   = lane >> 2;
    const int qc   = lane & 3;
    const int q0   = blockIdx.x * 64;
    const int bh   = blockIdx.y;

    const __half* Qg  = g_Qh + (size_t)bh * SEQ * HD;
    const __half* Kg  = g_Kh + (size_t)bh * SEQ * HD;
    const __half* Vtg = g_Vt + (size_t)bh * HD * SEQ;

    const int cr = tid >> 1;        // 0..63 row
    const int cs = tid & 1;         // 0..1 segment (32 halves)

    // Q tile (group 0)
    #pragma unroll
    for (int i = 0; i < 4; i++)
        CP16(sbase + AQ_OFF + (uint32_t)cr * GROW + cs * 64 + i * 16,
             Qg + (size_t)(q0 + cr) * HD + cs * 32 + i * 8);
    CP_COMMIT();

    auto issueKV = [&](int kt, int st) {
        #pragma unroll
        for (int i = 0; i < 4; i++) {
            CP16(sbase + AK_OFF(st) + (uint32_t)cr * GROW + cs * 64 + i * 16,
                 Kg + (size_t)(kt + cr) * HD + cs * 32 + i * 8);
            CP16(sbase + AV_OFF(st) + (uint32_t)cr * GROW + cs * 64 + i * 16,
                 Vtg + (size_t)cr * SEQ + kt + cs * 32 + i * 8);
        }
        CP_COMMIT();
    };

    issueKV(0, 0);     // group 1
    CP_WAIT1();        // Q ready
    __syncthreads();

    // Hoist Q A-fragments for whole kernel
    uint32_t aq[4][4];
    {
        const uint32_t* Q2 = (const uint32_t*)(smc + AQ_OFF);
        const int r = wid * 16 + qr;
        #pragma unroll
        for (int ks = 0; ks < 4; ks++) {
            const int c2 = ks * 8 + qc;
            aq[ks][0] = Q2[r * 36 + c2];
            aq[ks][1] = Q2[(r + 8) * 36 + c2];
            aq[ks][2] = Q2[r * 36 + c2 + 4];
            aq[ks][3] = Q2[(r + 8) * 36 + c2 + 4];
        }
    }

    float o[8][4] = {};
    float mr[2] = { -1e30f, -1e30f };
    float lr_[2] = { 0.f, 0.f };
    const float csc = 0.125f * 1.44269504f;  // 1/sqrt(64) * log2(e)

    const int NT = SEQ / 64;   // 32
    for (int t = 0; t < NT; t++) {
        const int st = t & 1;
        __syncthreads();                     // prior compute done before overwrite
        if (t + 1 < NT) { issueKV((t + 1) * 64, st ^ 1); CP_WAIT1(); }
        else            { CP_WAIT0(); }
        __syncthreads();                     // tile t visible to all warps

        const uint32_t* K2 = (const uint32_t*)(smc + AK_OFF(st));
        const uint32_t* V2 = (const uint32_t*)(smc + AV_OFF(st));

        // S = Q @ K^T
        float s[8][4] = {};
        #pragma unroll
        for (int nt = 0; nt < 8; nt++) {
            const uint32_t* pb = K2 + (nt * 8 + qr) * 36 + qc;
            #pragma unroll
            for (int ks = 0; ks < 4; ks++)
                mma16(s[nt], aq[ks], pb[ks * 8], pb[ks * 8 + 4]);
        }

        // Online softmax
        float tmax0 = -1e30f, tmax1 = -1e30f;
        #pragma unroll
        for (int nt = 0; nt < 8; nt++) {
            s[nt][0] *= csc; s[nt][1] *= csc; s[nt][2] *= csc; s[nt][3] *= csc;
            tmax0 = fmaxf(tmax0, fmaxf(s[nt][0], s[nt][1]));
            tmax1 = fmaxf(tmax1, fmaxf(s[nt][2], s[nt][3]));
        }
        tmax0 = fmaxf(tmax0, __shfl_xor_sync(0xffffffffu, tmax0, 1));
        tmax0 = fmaxf(tmax0, __shfl_xor_sync(0xffffffffu, tmax0, 2));
        tmax1 = fmaxf(tmax1, __shfl_xor_sync(0xffffffffu, tmax1, 1));
        tmax1 = fmaxf(tmax1, __shfl_xor_sync(0xffffffffu, tmax1, 2));
        const float mn0 = fmaxf(mr[0], tmax0);
        const float mn1 = fmaxf(mr[1], tmax1);
        const float corr0 = exp2f(mr[0] - mn0);
        const float corr1 = exp2f(mr[1] - mn1);
        mr[0] = mn0; mr[1] = mn1;

        float rs0 = 0.f, rs1 = 0.f;
        #pragma unroll
        for (int nt = 0; nt < 8; nt++) {
            s[nt][0] = exp2f(s[nt][0] - mn0);
            s[nt][1] = exp2f(s[nt][1] - mn0);
            s[nt][2] = exp2f(s[nt][2] - mn1);
            s[nt][3] = exp2f(s[nt][3] - mn1);
            rs0 += s[nt][0] + s[nt][1];
            rs1 += s[nt][2] + s[nt][3];
        }
        rs0 += __shfl_xor_sync(0xffffffffu, rs0, 1);
        rs0 += __shfl_xor_sync(0xffffffffu, rs0, 2);
        rs1 += __shfl_xor_sync(0xffffffffu, rs1, 1);
        rs1 += __shfl_xor_sync(0xffffffffu, rs1, 2);
        lr_[0] = lr_[0] * corr0 + rs0;
        lr_[1] = lr_[1] * corr1 + rs1;

        #pragma unroll
        for (int nt = 0; nt < 8; nt++) {
            o[nt][0] *= corr0; o[nt][1] *= corr0;
            o[nt][2] *= corr1; o[nt][3] *= corr1;
        }

        // Repack S C-frags -> PV A-frags (register-only, no smem)
        uint32_t ap[4][4];
        #pragma unroll
        for (int ks = 0; ks < 4; ks++) {
            ap[ks][0] = packh2(s[2 * ks][0],     s[2 * ks][1]);
            ap[ks][1] = packh2(s[2 * ks][2],     s[2 * ks][3]);
            ap[ks][2] = packh2(s[2 * ks + 1][0], s[2 * ks + 1][1]);
            ap[ks][3] = packh2(s[2 * ks + 1][2], s[2 * ks + 1][3]);
        }

        // O += P @ V   (B from pre-transposed V: natural rows)
        #pragma unroll
        for (int nt = 0; nt < 8; nt++) {
            const uint32_t* pv = V2 + (nt * 8 + qr) * 36 + qc;
            #pragma unroll
            for (int ks = 0; ks < 4; ks++)
                mma16(o[nt], ap[ks], pv[ks * 8], pv[ks * 8 + 4]);
        }
    }

    // Normalize, write O as half to g_Xh [B,S,HID]
    const int b = bh >> 4, h = bh & 15;
    const int q = q0 + wid * 16 + qr;
    const float inv0 = 1.f / lr_[0];
    const float inv1 = 1.f / lr_[1];
    __half* base0 = g_Xh + (size_t)(b * SEQ + q) * HID + h * HD;
    __half* base1 = g_Xh + (size_t)(b * SEQ + q + 8) * HID + h * HD;
    #pragma unroll
    for (int nt = 0; nt < 8; nt++) {
        const int col = nt * 8 + 2 * qc;
        *(uint32_t*)(base0 + col) = packh2(o[nt][0] * inv0, o[nt][1] * inv0);
        *(uint32_t*)(base1 + col) = packh2(o[nt][2] * inv1, o[nt][3] * inv1);
    }
}

// ---------------------------------------------------------------------------
extern "C" void kernel_launch(void* const* d_in, const int* in_sizes, int n_in,
                              void* d_out, int out_size)
{
    const float* query = (const float*)d_in[0];
    const float* key   = (const float*)d_in[1];
    const float* value = (const float*)d_in[2];
    const float* wq    = (const float*)d_in[3];
    const float* bq    = (const float*)d_in[4];
    const float* wk    = (const float*)d_in[5];
    const float* bk    = (const float*)d_in[6];
    const float* wv    = (const float*)d_in[7];
    const float* bv    = (const float*)d_in[8];
    const float* wf    = (const float*)d_in[9];
    const float* bf    = (const float*)d_in[10];
    float* out = (float*)d_out;

    cudaFuncSetAttribute(gemm_h, cudaFuncAttributeMaxDynamicSharedMemorySize,
                         GEMM_SMEM);
    cudaFuncSetAttribute(attn_h, cudaFuncAttributeMaxDynamicSharedMemorySize,
                         ATTN_SMEM);

    // 1) fp32 -> fp16 conversion of X inputs + weights
    cvt_h<<<(N4TOT + 255) / 256, 256>>>(query, key, value, wq, wk, wv, wf);

    // 2) Q,K,V projections in one launch (blockIdx.z = which)
    dim3 gq(HID / 128, MTOT / 128, 3);
    gemm_h<<<gq, 128, GEMM_SMEM>>>(bq, bk, bv, nullptr, 0);

    // 3) attention
    dim3 ga(SEQ / 64, BATCH * NH);
    attn_h<<<ga, 128, ATTN_SMEM>>>();

    // 4) final projection (reads g_Xh, writes fp32 out)
    dim3 gf(HID / 128, MTOT / 128, 1);
    gemm_h<<<gf, 128, GEMM_SMEM>>>(bf, nullptr, nullptr, out, 1);
}

// round 7
// speedup vs baseline: 6.9274x; 1.0398x over previous
#include <cuda_runtime.h>
#include <cuda_fp16.h>
#include <cstdint>

#define HID   1024
#define NH    16
#define HD    64
#define BATCH 4
#define SEQ   2048
#define MTOT  (BATCH*SEQ)   // 8192

// Scratch (allocation-free rule: __device__ globals). All fp16.
__device__ __align__(16) __half h_Xq[(size_t)MTOT * HID];
__device__ __align__(16) __half h_Xk[(size_t)MTOT * HID];
__device__ __align__(16) __half h_Xv[(size_t)MTOT * HID];
__device__ __align__(16) __half h_Wq[(size_t)HID * HID];
__device__ __align__(16) __half h_Wk[(size_t)HID * HID];
__device__ __align__(16) __half h_Wv[(size_t)HID * HID];
__device__ __align__(16) __half h_Wf[(size_t)HID * HID];
__device__ __align__(16) __half g_Qh[(size_t)MTOT * HID];   // [B,H,S,D]
__device__ __align__(16) __half g_Kh[(size_t)MTOT * HID];   // [B,H,S,D]
__device__ __align__(16) __half g_Vt[(size_t)MTOT * HID];   // [B,H,D,S]  (transposed)
__device__ __align__(16) __half g_Xh[(size_t)MTOT * HID];   // [B,S,HID]

// ---------------------------------------------------------------------------
static __device__ __forceinline__ uint32_t smem_u32(const void* p) {
    uint32_t a;
    asm("{ .reg .u64 t; cvta.to.shared.u64 t, %1; cvt.u32.u64 %0, t; }"
        : "=r"(a) : "l"(p));
    return a;
}
// D += A*B  (m16n8k16, f16 inputs, f32 accum)
static __device__ __forceinline__ void mma16(float* d, const uint32_t* a,
                                             uint32_t b0, uint32_t b1) {
    asm volatile(
        "mma.sync.aligned.m16n8k16.row.col.f32.f16.f16.f32 "
        "{%0,%1,%2,%3}, {%4,%5,%6,%7}, {%8,%9}, {%0,%1,%2,%3};"
        : "+f"(d[0]), "+f"(d[1]), "+f"(d[2]), "+f"(d[3])
        : "r"(a[0]), "r"(a[1]), "r"(a[2]), "r"(a[3]), "r"(b0), "r"(b1));
}
// One ldmatrix.x4: four 8x8 b16 tiles -> 4 regs in mma fragment layout
static __device__ __forceinline__ void ldsm4(uint32_t& r0, uint32_t& r1,
                                             uint32_t& r2, uint32_t& r3,
                                             uint32_t addr) {
    asm volatile("ldmatrix.sync.aligned.m8n8.x4.shared.b16 {%0,%1,%2,%3}, [%4];"
                 : "=r"(r0), "=r"(r1), "=r"(r2), "=r"(r3) : "r"(addr));
}
static __device__ __forceinline__ uint32_t packh2(float x, float y) {
    __half2 h = __floats2half2_rn(x, y);
    return *(uint32_t*)&h;
}
#define CP16(dst, src) \
    asm volatile("cp.async.cg.shared.global [%0], [%1], 16;" :: "r"(dst), "l"(src) : "memory")
#define CP_COMMIT() asm volatile("cp.async.commit_group;" ::: "memory")
#define CP_WAIT1()  asm volatile("cp.async.wait_group 1;" ::: "memory")
#define CP_WAIT0()  asm volatile("cp.async.wait_group 0;" ::: "memory")

// ldmatrix per-lane pointer offsets (bytes), row stride GROW.
// A-frag (16x16): lanes 0-15 -> rows 0-15 col 0; lanes 16-31 -> rows 0-15 col 8.
// B-frag pair (16 rows x 16 k): lanes 0-7 rows0-7 k0 | 8-15 rows0-7 k8 |
//                               16-23 rows8-15 k0 | 24-31 rows8-15 k8.
#define GROW 144
static __device__ __forceinline__ uint32_t lane_off_A(int lane) {
    return (uint32_t)(lane & 15) * GROW + (uint32_t)(lane >> 4) * 16;
}
static __device__ __forceinline__ uint32_t lane_off_B(int lane) {
    const int row = (lane & 7) + ((lane >> 4) & 1) * 8;
    const int colh = ((lane >> 3) & 1) * 8;
    return (uint32_t)row * GROW + (uint32_t)colh * 2;
}

// ---------------------------------------------------------------------------
// fp32 -> fp16 convert: 3 X inputs + 4 weights.
// ---------------------------------------------------------------------------
#define N4X (MTOT * HID / 4)   // 2097152
#define N4W (HID * HID / 4)    // 262144
#define N4TOT (3 * N4X + 4 * N4W)

__global__ __launch_bounds__(256) void cvt_h(
    const float* __restrict__ q, const float* __restrict__ k,
    const float* __restrict__ v,
    const float* __restrict__ wq, const float* __restrict__ wk,
    const float* __restrict__ wv, const float* __restrict__ wf)
{
    const int id = blockIdx.x * 256 + threadIdx.x;
    if (id >= N4TOT) return;
    const float* src; __half* dst; int off;
    if (id < N4X)              { src = q;  dst = h_Xq; off = id; }
    else if (id < 2 * N4X)     { src = k;  dst = h_Xk; off = id - N4X; }
    else if (id < 3 * N4X)     { src = v;  dst = h_Xv; off = id - 2 * N4X; }
    else {
        int w = id - 3 * N4X;
        if (w < N4W)           { src = wq; dst = h_Wq; off = w; }
        else if (w < 2 * N4W)  { src = wk; dst = h_Wk; off = w - N4W; }
        else if (w < 3 * N4W)  { src = wv; dst = h_Wv; off = w - 2 * N4W; }
        else                   { src = wf; dst = h_Wf; off = w - 3 * N4W; }
    }
    float4 x = *(const float4*)(src + (size_t)off * 4);
    uint2 o;
    o.x = packh2(x.x, x.y);
    o.y = packh2(x.z, x.w);
    *(uint2*)(dst + (size_t)off * 4) = o;
}

// ---------------------------------------------------------------------------
// fp16 GEMM, ldmatrix fragment loads.
// CTA 128x128, BK=64, 128 thr (4 warps 2x2), warp tile 64x64, 3-stage cp.async.
// ---------------------------------------------------------------------------
#define GSTG  (2 * 128 * GROW)            // 36864 B per stage (A then B)
#define GEMM_SMEM (3 * GSTG)              // 110592 B

__global__ __launch_bounds__(128, 2) void gemm_h(
    const float* __restrict__ Bq, const float* __restrict__ Bk,
    const float* __restrict__ Bv, float* __restrict__ outFinal, int mode)
{
    extern __shared__ char smc[];
    const uint32_t sbase = smem_u32(smc);

    const int which = (mode == 0) ? (int)blockIdx.z : 3;
    const __half* Xp; const __half* W; const float* bias;
    if (which == 0)      { Xp = h_Xq; W = h_Wq; bias = Bq; }
    else if (which == 1) { Xp = h_Xk; W = h_Wk; bias = Bk; }
    else if (which == 2) { Xp = h_Xv; W = h_Wv; bias = Bv; }
    else                 { Xp = g_Xh; W = h_Wf; bias = Bq; }

    const int tid  = threadIdx.x;
    const int wid  = tid >> 5;
    const int lane = tid & 31;
    const int wm   = wid >> 1;
    const int wn   = wid & 1;
    const int qr   = lane >> 2;
    const int qc   = lane & 3;
    const int m0   = blockIdx.y * 128;
    const int n0   = blockIdx.x * 128;

    // cp.async one K-chunk: A 128x64h + B 128x64h
    auto issue = [&](int kc) {
        const uint32_t sA = sbase + (kc % 3) * GSTG;
        const uint32_t sB = sA + 128 * GROW;
        #pragma unroll
        for (int c = 0; c < 8; c++) {
            const int g   = c * 128 + tid;
            const int row = g >> 3;
            const int seg = g & 7;
            const uint32_t off = (uint32_t)row * GROW + seg * 16;
            CP16(sA + off, Xp + (size_t)(m0 + row) * HID + kc * 64 + seg * 8);
            CP16(sB + off, W  + (size_t)(n0 + row) * HID + kc * 64 + seg * 8);
        }
        CP_COMMIT();
    };

    // ldmatrix lane offsets (within a stage)
    const uint32_t offA = lane_off_A(lane);
    const uint32_t offB = lane_off_B(lane);
    uint32_t aAddr[4], bAddr[4];
    #pragma unroll
    for (int mt = 0; mt < 4; mt++)
        aAddr[mt] = (uint32_t)(wm * 64 + mt * 16) * GROW + offA;
    #pragma unroll
    for (int np = 0; np < 4; np++)
        bAddr[np] = 128 * GROW + (uint32_t)(wn * 64 + np * 16) * GROW + offB;

    float acc[4][8][4] = {};

    issue(0);
    issue(1);

    const int NKC = HID / 64;   // 16
    for (int kc = 0; kc < NKC; kc++) {
        if (kc + 1 < NKC) CP_WAIT1(); else CP_WAIT0();
        __syncthreads();
        if (kc + 2 < NKC) issue(kc + 2);

        const uint32_t stg = sbase + (kc % 3) * GSTG;
        #pragma unroll
        for (int ks = 0; ks < 4; ks++) {
            uint32_t af[4][4], bf[8][2];
            #pragma unroll
            for (int mt = 0; mt < 4; mt++)
                ldsm4(af[mt][0], af[mt][1], af[mt][2], af[mt][3],
                      stg + aAddr[mt] + ks * 32);
            #pragma unroll
            for (int np = 0; np < 4; np++)
                ldsm4(bf[2 * np][0], bf[2 * np][1], bf[2 * np + 1][0],
                      bf[2 * np + 1][1], stg + bAddr[np] + ks * 32);
            #pragma unroll
            for (int mt = 0; mt < 4; mt++)
                #pragma unroll
                for (int nt = 0; nt < 8; nt++)
                    mma16(acc[mt][nt], af[mt], bf[nt][0], bf[nt][1]);
        }
    }

    // Epilogue
    #pragma unroll
    for (int mt = 0; mt < 4; mt++) {
        const int m = m0 + wm * 64 + mt * 16 + qr;
        #pragma unroll
        for (int nt = 0; nt < 8; nt++) {
            const int n = n0 + wn * 64 + nt * 8 + 2 * qc;
            const float b0 = bias[n], b1 = bias[n + 1];
            const float v00 = acc[mt][nt][0] + b0, v01 = acc[mt][nt][1] + b1;
            const float v10 = acc[mt][nt][2] + b0, v11 = acc[mt][nt][3] + b1;
            if (which == 3) {
                *(float2*)(outFinal + (size_t)m * HID + n)       = make_float2(v00, v01);
                *(float2*)(outFinal + (size_t)(m + 8) * HID + n) = make_float2(v10, v11);
            } else {
                const int bb = m >> 11, s = m & 2047;
                const int h = n >> 6,  d = n & 63;
                if (which == 2) {
                    __half* base = g_Vt + ((size_t)(bb * NH + h) * HD) * SEQ;
                    base[(size_t)(d + 0) * SEQ + s]     = __float2half(v00);
                    base[(size_t)(d + 1) * SEQ + s]     = __float2half(v01);
                    base[(size_t)(d + 0) * SEQ + s + 8] = __float2half(v10);
                    base[(size_t)(d + 1) * SEQ + s + 8] = __float2half(v11);
                } else {
                    __half* outh = (which == 0) ? g_Qh : g_Kh;
                    __half* base = outh + ((size_t)(bb * NH + h) * SEQ) * HD + d;
                    *(uint32_t*)(base + (size_t)s * HD)       = packh2(v00, v01);
                    *(uint32_t*)(base + (size_t)(s + 8) * HD) = packh2(v10, v11);
                }
            }
        }
    }
}

// ---------------------------------------------------------------------------
// fp16 flash attention, ldmatrix fragment loads.
// Br=Bc=64, head_dim=64, 4 warps. K natural, V pre-transposed [d][kv].
// P repacked register-only (no smem round-trip).
// ---------------------------------------------------------------------------
#define AQ_OFF 0
#define AK_OFF(st) (9216 + (st) * 9216)
#define AV_OFF(st) (27648 + (st) * 9216)
#define ATTN_SMEM 46080

__global__ __launch_bounds__(128, 4) void attn_h()
{
    extern __shared__ char smc[];
    const uint32_t sbase = smem_u32(smc);

    const int tid  = threadIdx.x;
    const int wid  = tid >> 5;
    const int lane = tid & 31;
    const int qr   = lane >> 2;
    const int qc   = lane & 3;
    const int q0   = blockIdx.x * 64;
    const int bh   = blockIdx.y;

    const __half* Qg  = g_Qh + (size_t)bh * SEQ * HD;
    const __half* Kg  = g_Kh + (size_t)bh * SEQ * HD;
    const __half* Vtg = g_Vt + (size_t)bh * HD * SEQ;

    const int cr = tid >> 1;        // 0..63 row
    const int cs = tid & 1;         // 0..1 segment (32 halves)

    // Q tile (group 0)
    #pragma unroll
    for (int i = 0; i < 4; i++)
        CP16(sbase + AQ_OFF + (uint32_t)cr * GROW + cs * 64 + i * 16,
             Qg + (size_t)(q0 + cr) * HD + cs * 32 + i * 8);
    CP_COMMIT();

    auto issueKV = [&](int kt, int st) {
        #pragma unroll
        for (int i = 0; i < 4; i++) {
            CP16(sbase + AK_OFF(st) + (uint32_t)cr * GROW + cs * 64 + i * 16,
                 Kg + (size_t)(kt + cr) * HD + cs * 32 + i * 8);
            CP16(sbase + AV_OFF(st) + (uint32_t)cr * GROW + cs * 64 + i * 16,
                 Vtg + (size_t)cr * SEQ + kt + cs * 32 + i * 8);
        }
        CP_COMMIT();
    };

    issueKV(0, 0);     // group 1
    CP_WAIT1();        // Q ready
    __syncthreads();

    const uint32_t offA = lane_off_A(lane);
    const uint32_t offB = lane_off_B(lane);

    // Hoist Q A-fragments for whole kernel
    uint32_t aq[4][4];
    {
        const uint32_t qa = sbase + AQ_OFF + (uint32_t)(wid * 16) * GROW + offA;
        #pragma unroll
        for (int ks = 0; ks < 4; ks++)
            ldsm4(aq[ks][0], aq[ks][1], aq[ks][2], aq[ks][3], qa + ks * 32);
    }

    uint32_t bOff[4];
    #pragma unroll
    for (int np = 0; np < 4; np++)
        bOff[np] = (uint32_t)(np * 16) * GROW + offB;

    float o[8][4] = {};
    float mr[2] = { -1e30f, -1e30f };
    float lr_[2] = { 0.f, 0.f };
    const float csc = 0.125f * 1.44269504f;  // 1/sqrt(64) * log2(e)

    const int NT = SEQ / 64;   // 32
    for (int t = 0; t < NT; t++) {
        const int st = t & 1;
        __syncthreads();
        if (t + 1 < NT) { issueKV((t + 1) * 64, st ^ 1); CP_WAIT1(); }
        else            { CP_WAIT0(); }
        __syncthreads();

        const uint32_t kb = sbase + AK_OFF(st);
        const uint32_t vb = sbase + AV_OFF(st);

        // S = Q @ K^T
        float s[8][4] = {};
        #pragma unroll
        for (int np = 0; np < 4; np++) {
            #pragma unroll
            for (int ks = 0; ks < 4; ks++) {
                uint32_t b0, b1, b2, b3;
                ldsm4(b0, b1, b2, b3, kb + bOff[np] + ks * 32);
                mma16(s[2 * np],     aq[ks], b0, b1);
                mma16(s[2 * np + 1], aq[ks], b2, b3);
            }
        }

        // Online softmax
        float tmax0 = -1e30f, tmax1 = -1e30f;
        #pragma unroll
        for (int nt = 0; nt < 8; nt++) {
            s[nt][0] *= csc; s[nt][1] *= csc; s[nt][2] *= csc; s[nt][3] *= csc;
            tmax0 = fmaxf(tmax0, fmaxf(s[nt][0], s[nt][1]));
            tmax1 = fmaxf(tmax1, fmaxf(s[nt][2], s[nt][3]));
        }
        tmax0 = fmaxf(tmax0, __shfl_xor_sync(0xffffffffu, tmax0, 1));
        tmax0 = fmaxf(tmax0, __shfl_xor_sync(0xffffffffu, tmax0, 2));
        tmax1 = fmaxf(tmax1, __shfl_xor_sync(0xffffffffu, tmax1, 1));
        tmax1 = fmaxf(tmax1, __shfl_xor_sync(0xffffffffu, tmax1, 2));
        const float mn0 = fmaxf(mr[0], tmax0);
        const float mn1 = fmaxf(mr[1], tmax1);
        const float corr0 = exp2f(mr[0] - mn0);
        const float corr1 = exp2f(mr[1] - mn1);
        mr[0] = mn0; mr[1] = mn1;

        float rs0 = 0.f, rs1 = 0.f;
        #pragma unroll
        for (int nt = 0; nt < 8; nt++) {
            s[nt][0] = exp2f(s[nt][0] - mn0);
            s[nt][1] = exp2f(s[nt][1] - mn0);
            s[nt][2] = exp2f(s[nt][2] - mn1);
            s[nt][3] = exp2f(s[nt][3] - mn1);
            rs0 += s[nt][0] + s[nt][1];
            rs1 += s[nt][2] + s[nt][3];
        }
        rs0 += __shfl_xor_sync(0xffffffffu, rs0, 1);
        rs0 += __shfl_xor_sync(0xffffffffu, rs0, 2);
        rs1 += __shfl_xor_sync(0xffffffffu, rs1, 1);
        rs1 += __shfl_xor_sync(0xffffffffu, rs1, 2);
        lr_[0] = lr_[0] * corr0 + rs0;
        lr_[1] = lr_[1] * corr1 + rs1;

        #pragma unroll
        for (int nt = 0; nt < 8; nt++) {
            o[nt][0] *= corr0; o[nt][1] *= corr0;
            o[nt][2] *= corr1; o[nt][3] *= corr1;
        }

        // Repack S C-frags -> PV A-frags (register-only)
        uint32_t ap[4][4];
        #pragma unroll
        for (int ks = 0; ks < 4; ks++) {
            ap[ks][0] = packh2(s[2 * ks][0],     s[2 * ks][1]);
            ap[ks][1] = packh2(s[2 * ks][2],     s[2 * ks][3]);
            ap[ks][2] = packh2(s[2 * ks + 1][0], s[2 * ks + 1][1]);
            ap[ks][3] = packh2(s[2 * ks + 1][2], s[2 * ks + 1][3]);
        }

        // O += P @ V
        #pragma unroll
        for (int np = 0; np < 4; np++) {
            #pragma unroll
            for (int ks = 0; ks < 4; ks++) {
                uint32_t b0, b1, b2, b3;
                ldsm4(b0, b1, b2, b3, vb + bOff[np] + ks * 32);
                mma16(o[2 * np],     ap[ks], b0, b1);
                mma16(o[2 * np + 1], ap[ks], b2, b3);
            }
        }
    }

    // Normalize, write O as half to g_Xh [B,S,HID]
    const int b = bh >> 4, h = bh & 15;
    const int q = q0 + wid * 16 + qr;
    const float inv0 = 1.f / lr_[0];
    const float inv1 = 1.f / lr_[1];
    __half* base0 = g_Xh + (size_t)(b * SEQ + q) * HID + h * HD;
    __half* base1 = g_Xh + (size_t)(b * SEQ + q + 8) * HID + h * HD;
    #pragma unroll
    for (int nt = 0; nt < 8; nt++) {
        const int col = nt * 8 + 2 * qc;
        *(uint32_t*)(base0 + col) = packh2(o[nt][0] * inv0, o[nt][1] * inv0);
        *(uint32_t*)(base1 + col) = packh2(o[nt][2] * inv1, o[nt][3] * inv1);
    }
}

// ---------------------------------------------------------------------------
extern "C" void kernel_launch(void* const* d_in, const int* in_sizes, int n_in,
                              void* d_out, int out_size)
{
    const float* query = (const float*)d_in[0];
    const float* key   = (const float*)d_in[1];
    const float* value = (const float*)d_in[2];
    const float* wq    = (const float*)d_in[3];
    const float* bq    = (const float*)d_in[4];
    const float* wk    = (const float*)d_in[5];
    const float* bk    = (const float*)d_in[6];
    const float* wv    = (const float*)d_in[7];
    const float* bv    = (const float*)d_in[8];
    const float* wf    = (const float*)d_in[9];
    const float* bf    = (const float*)d_in[10];
    float* out = (float*)d_out;

    cudaFuncSetAttribute(gemm_h, cudaFuncAttributeMaxDynamicSharedMemorySize,
                         GEMM_SMEM);
    cudaFuncSetAttribute(attn_h, cudaFuncAttributeMaxDynamicSharedMemorySize,
                         ATTN_SMEM);

    cvt_h<<<(N4TOT + 255) / 256, 256>>>(query, key, value, wq, wk, wv, wf);

    dim3 gq(HID / 128, MTOT / 128, 3);
    gemm_h<<<gq, 128, GEMM_SMEM>>>(bq, bk, bv, nullptr, 0);

    dim3 ga(SEQ / 64, BATCH * NH);
    attn_h<<<ga, 128, ATTN_SMEM>>>();

    dim3 gf(HID / 128, MTOT / 128, 1);
    gemm_h<<<gf, 128, GEMM_SMEM>>>(bf, nullptr, nullptr, out, 1);
}

// round 8
// speedup vs baseline: 7.0980x; 1.0246x over previous
#include <cuda_runtime.h>
#include <cuda_fp16.h>
#include <cstdint>

#define HID   1024
#define NH    16
#define HD    64
#define BATCH 4
#define SEQ   2048
#define MTOT  (BATCH*SEQ)   // 8192

// Scratch (allocation-free rule: __device__ globals). All fp16.
__device__ __align__(16) __half h_Xq[(size_t)MTOT * HID];
__device__ __align__(16) __half h_Xk[(size_t)MTOT * HID];
__device__ __align__(16) __half h_Xv[(size_t)MTOT * HID];
__device__ __align__(16) __half h_Wq[(size_t)HID * HID];
__device__ __align__(16) __half h_Wk[(size_t)HID * HID];
__device__ __align__(16) __half h_Wv[(size_t)HID * HID];
__device__ __align__(16) __half h_Wf[(size_t)HID * HID];
__device__ __align__(16) __half g_Qh[(size_t)MTOT * HID];   // [B,H,S,D], pre-scaled by 1/8*log2e
__device__ __align__(16) __half g_Kh[(size_t)MTOT * HID];   // [B,H,S,D]
__device__ __align__(16) __half g_Vt[(size_t)MTOT * HID];   // [B,H,D,S]  (transposed)
__device__ __align__(16) __half g_Xh[(size_t)MTOT * HID];   // [B,S,HID]

#define QSCALE (0.125f * 1.44269504f)   // 1/sqrt(64) * log2(e), folded into Q

// ---------------------------------------------------------------------------
static __device__ __forceinline__ uint32_t smem_u32(const void* p) {
    uint32_t a;
    asm("{ .reg .u64 t; cvta.to.shared.u64 t, %1; cvt.u32.u64 %0, t; }"
        : "=r"(a) : "l"(p));
    return a;
}
// D += A*B  (m16n8k16, f16 inputs, f32 accum)
static __device__ __forceinline__ void mma16(float* d, const uint32_t* a,
                                             uint32_t b0, uint32_t b1) {
    asm volatile(
        "mma.sync.aligned.m16n8k16.row.col.f32.f16.f16.f32 "
        "{%0,%1,%2,%3}, {%4,%5,%6,%7}, {%8,%9}, {%0,%1,%2,%3};"
        : "+f"(d[0]), "+f"(d[1]), "+f"(d[2]), "+f"(d[3])
        : "r"(a[0]), "r"(a[1]), "r"(a[2]), "r"(a[3]), "r"(b0), "r"(b1));
}
static __device__ __forceinline__ void ldsm4(uint32_t& r0, uint32_t& r1,
                                             uint32_t& r2, uint32_t& r3,
                                             uint32_t addr) {
    asm volatile("ldmatrix.sync.aligned.m8n8.x4.shared.b16 {%0,%1,%2,%3}, [%4];"
                 : "=r"(r0), "=r"(r1), "=r"(r2), "=r"(r3) : "r"(addr));
}
static __device__ __forceinline__ uint32_t packh2(float x, float y) {
    __half2 h = __floats2half2_rn(x, y);
    return *(uint32_t*)&h;
}
#define CP16(dst, src) \
    asm volatile("cp.async.cg.shared.global [%0], [%1], 16;" :: "r"(dst), "l"(src) : "memory")
#define CP_COMMIT() asm volatile("cp.async.commit_group;" ::: "memory")
#define CP_WAIT1()  asm volatile("cp.async.wait_group 1;" ::: "memory")
#define CP_WAIT0()  asm volatile("cp.async.wait_group 0;" ::: "memory")

#define GROW 144
static __device__ __forceinline__ uint32_t lane_off_A(int lane) {
    return (uint32_t)(lane & 15) * GROW + (uint32_t)(lane >> 4) * 16;
}
static __device__ __forceinline__ uint32_t lane_off_B(int lane) {
    const int row = (lane & 7) + ((lane >> 4) & 1) * 8;
    const int colh = ((lane >> 3) & 1) * 8;
    return (uint32_t)row * GROW + (uint32_t)colh * 2;
}

// ---------------------------------------------------------------------------
// fp32 -> fp16 convert: 3 X inputs + 4 weights.
// ---------------------------------------------------------------------------
#define N4X (MTOT * HID / 4)   // 2097152
#define N4W (HID * HID / 4)    // 262144
#define N4TOT (3 * N4X + 4 * N4W)

__global__ __launch_bounds__(256) void cvt_h(
    const float* __restrict__ q, const float* __restrict__ k,
    const float* __restrict__ v,
    const float* __restrict__ wq, const float* __restrict__ wk,
    const float* __restrict__ wv, const float* __restrict__ wf)
{
    const int id = blockIdx.x * 256 + threadIdx.x;
    if (id >= N4TOT) return;
    const float* src; __half* dst; int off;
    if (id < N4X)              { src = q;  dst = h_Xq; off = id; }
    else if (id < 2 * N4X)     { src = k;  dst = h_Xk; off = id - N4X; }
    else if (id < 3 * N4X)     { src = v;  dst = h_Xv; off = id - 2 * N4X; }
    else {
        int w = id - 3 * N4X;
        if (w < N4W)           { src = wq; dst = h_Wq; off = w; }
        else if (w < 2 * N4W)  { src = wk; dst = h_Wk; off = w - N4W; }
        else if (w < 3 * N4W)  { src = wv; dst = h_Wv; off = w - 2 * N4W; }
        else                   { src = wf; dst = h_Wf; off = w - 3 * N4W; }
    }
    float4 x = *(const float4*)(src + (size_t)off * 4);
    uint2 o;
    o.x = packh2(x.x, x.y);
    o.y = packh2(x.z, x.w);
    *(uint2*)(dst + (size_t)off * 4) = o;
}

// ---------------------------------------------------------------------------
// fp16 GEMM. CTA 128x128, BK=64, 256 thr = 8 warps (2m x 4n), warp tile 64x32.
// 3-stage cp.async, ldmatrix frag loads. 2 CTAs/SM -> 16 warps/SM.
// mode 0: z=which {0,1,2}: Q (pre-scaled) / K -> [B,H,S,D]; V -> [B,H,D,S].
// mode 1: X=g_Xh, W=h_Wf, fp32 row-major store to out.
// ---------------------------------------------------------------------------
#define GSTG  (2 * 128 * GROW)            // 36864 B per stage (A then B)
#define GEMM_SMEM (3 * GSTG)              // 110592 B

__global__ __launch_bounds__(256, 2) void gemm_h(
    const float* __restrict__ Bq, const float* __restrict__ Bk,
    const float* __restrict__ Bv, float* __restrict__ outFinal, int mode)
{
    extern __shared__ char smc[];
    const uint32_t sbase = smem_u32(smc);

    const int which = (mode == 0) ? (int)blockIdx.z : 3;
    const __half* Xp; const __half* W; const float* bias;
    if (which == 0)      { Xp = h_Xq; W = h_Wq; bias = Bq; }
    else if (which == 1) { Xp = h_Xk; W = h_Wk; bias = Bk; }
    else if (which == 2) { Xp = h_Xv; W = h_Wv; bias = Bv; }
    else                 { Xp = g_Xh; W = h_Wf; bias = Bq; }

    const int tid  = threadIdx.x;
    const int wid  = tid >> 5;
    const int lane = tid & 31;
    const int wm   = wid & 1;         // 0..1  (64-row block)
    const int wn   = wid >> 1;        // 0..3  (32-col block)
    const int qr   = lane >> 2;
    const int qc   = lane & 3;
    const int m0   = blockIdx.y * 128;
    const int n0   = blockIdx.x * 128;

    // cp.async one K-chunk: A 128x64h + B 128x64h, 256 threads
    auto issue = [&](int kc) {
        const uint32_t sA = sbase + (kc % 3) * GSTG;
        #pragma unroll
        for (int c = 0; c < 4; c++) {
            const int g   = c * 256 + tid;        // 0..1023
            const int row = g >> 3;               // 0..127
            const int seg = g & 7;
            const uint32_t off = (uint32_t)row * GROW + seg * 16;
            CP16(sA + off, Xp + (size_t)(m0 + row) * HID + kc * 64 + seg * 8);
            CP16(sA + 128 * GROW + off,
                 W + (size_t)(n0 + row) * HID + kc * 64 + seg * 8);
        }
        CP_COMMIT();
    };

    const uint32_t offA = lane_off_A(lane);
    const uint32_t offB = lane_off_B(lane);
    uint32_t aAddr[4], bAddr[2];
    #pragma unroll
    for (int mt = 0; mt < 4; mt++)
        aAddr[mt] = (uint32_t)(wm * 64 + mt * 16) * GROW + offA;
    #pragma unroll
    for (int np = 0; np < 2; np++)
        bAddr[np] = 128 * GROW + (uint32_t)(wn * 32 + np * 16) * GROW + offB;

    float acc[4][4][4] = {};

    issue(0);
    issue(1);

    const int NKC = HID / 64;   // 16
    for (int kc = 0; kc < NKC; kc++) {
        if (kc + 1 < NKC) CP_WAIT1(); else CP_WAIT0();
        __syncthreads();
        if (kc + 2 < NKC) issue(kc + 2);

        const uint32_t stg = sbase + (kc % 3) * GSTG;
        #pragma unroll
        for (int ks = 0; ks < 4; ks++) {
            uint32_t af[4][4], bf[4][2];
            #pragma unroll
            for (int mt = 0; mt < 4; mt++)
                ldsm4(af[mt][0], af[mt][1], af[mt][2], af[mt][3],
                      stg + aAddr[mt] + ks * 32);
            #pragma unroll
            for (int np = 0; np < 2; np++)
                ldsm4(bf[2 * np][0], bf[2 * np][1], bf[2 * np + 1][0],
                      bf[2 * np + 1][1], stg + bAddr[np] + ks * 32);
            #pragma unroll
            for (int mt = 0; mt < 4; mt++)
                #pragma unroll
                for (int nt = 0; nt < 4; nt++)
                    mma16(acc[mt][nt], af[mt], bf[nt][0], bf[nt][1]);
        }
    }

    // Epilogue
    const float oscale = (which == 0) ? QSCALE : 1.0f;
    #pragma unroll
    for (int mt = 0; mt < 4; mt++) {
        const int m = m0 + wm * 64 + mt * 16 + qr;
        #pragma unroll
        for (int nt = 0; nt < 4; nt++) {
            const int n = n0 + wn * 32 + nt * 8 + 2 * qc;
            const float b0 = bias[n], b1 = bias[n + 1];
            const float v00 = acc[mt][nt][0] + b0, v01 = acc[mt][nt][1] + b1;
            const float v10 = acc[mt][nt][2] + b0, v11 = acc[mt][nt][3] + b1;
            if (which == 3) {
                *(float2*)(outFinal + (size_t)m * HID + n)       = make_float2(v00, v01);
                *(float2*)(outFinal + (size_t)(m + 8) * HID + n) = make_float2(v10, v11);
            } else {
                const int bb = m >> 11, s = m & 2047;
                const int h = n >> 6,  d = n & 63;
                if (which == 2) {
                    __half* base = g_Vt + ((size_t)(bb * NH + h) * HD) * SEQ;
                    base[(size_t)(d + 0) * SEQ + s]     = __float2half(v00);
                    base[(size_t)(d + 1) * SEQ + s]     = __float2half(v01);
                    base[(size_t)(d + 0) * SEQ + s + 8] = __float2half(v10);
                    base[(size_t)(d + 1) * SEQ + s + 8] = __float2half(v11);
                } else {
                    __half* outh = (which == 0) ? g_Qh : g_Kh;
                    __half* base = outh + ((size_t)(bb * NH + h) * SEQ) * HD + d;
                    *(uint32_t*)(base + (size_t)s * HD) =
                        packh2(v00 * oscale, v01 * oscale);
                    *(uint32_t*)(base + (size_t)(s + 8) * HD) =
                        packh2(v10 * oscale, v11 * oscale);
                }
            }
        }
    }
}

// ---------------------------------------------------------------------------
// fp16 flash attention. Br=Bc=64, head_dim=64, 4 warps.
// Q pre-scaled (S is directly base-2 logits). K natural, V transposed [d][kv].
// P repacked register-only.
// ---------------------------------------------------------------------------
#define AQ_OFF 0
#define AK_OFF(st) (9216 + (st) * 9216)
#define AV_OFF(st) (27648 + (st) * 9216)
#define ATTN_SMEM 46080

__global__ __launch_bounds__(128, 4) void attn_h()
{
    extern __shared__ char smc[];
    const uint32_t sbase = smem_u32(smc);

    const int tid  = threadIdx.x;
    const int wid  = tid >> 5;
    const int lane = tid & 31;
    const int qr   = lane >> 2;
    const int qc   = lane & 3;
    const int q0   = blockIdx.x * 64;
    const int bh   = blockIdx.y;

    const __half* Qg  = g_Qh + (size_t)bh * SEQ * HD;
    const __half* Kg  = g_Kh + (size_t)bh * SEQ * HD;
    const __half* Vtg = g_Vt + (size_t)bh * HD * SEQ;

    const int cr = tid >> 1;
    const int cs = tid & 1;

    #pragma unroll
    for (int i = 0; i < 4; i++)
        CP16(sbase + AQ_OFF + (uint32_t)cr * GROW + cs * 64 + i * 16,
             Qg + (size_t)(q0 + cr) * HD + cs * 32 + i * 8);
    CP_COMMIT();

    auto issueKV = [&](int kt, int st) {
        #pragma unroll
        for (int i = 0; i < 4; i++) {
            CP16(sbase + AK_OFF(st) + (uint32_t)cr * GROW + cs * 64 + i * 16,
                 Kg + (size_t)(kt + cr) * HD + cs * 32 + i * 8);
            CP16(sbase + AV_OFF(st) + (uint32_t)cr * GROW + cs * 64 + i * 16,
                 Vtg + (size_t)cr * SEQ + kt + cs * 32 + i * 8);
        }
        CP_COMMIT();
    };

    issueKV(0, 0);
    CP_WAIT1();
    __syncthreads();

    const uint32_t offA = lane_off_A(lane);
    const uint32_t offB = lane_off_B(lane);

    uint32_t aq[4][4];
    {
        const uint32_t qa = sbase + AQ_OFF + (uint32_t)(wid * 16) * GROW + offA;
        #pragma unroll
        for (int ks = 0; ks < 4; ks++)
            ldsm4(aq[ks][0], aq[ks][1], aq[ks][2], aq[ks][3], qa + ks * 32);
    }

    uint32_t bOff[4];
    #pragma unroll
    for (int np = 0; np < 4; np++)
        bOff[np] = (uint32_t)(np * 16) * GROW + offB;

    float o[8][4] = {};
    float mr[2] = { -1e30f, -1e30f };
    float lr_[2] = { 0.f, 0.f };

    const int NT = SEQ / 64;   // 32
    for (int t = 0; t < NT; t++) {
        const int st = t & 1;
        __syncthreads();
        if (t + 1 < NT) { issueKV((t + 1) * 64, st ^ 1); CP_WAIT1(); }
        else            { CP_WAIT0(); }
        __syncthreads();

        const uint32_t kb = sbase + AK_OFF(st);
        const uint32_t vb = sbase + AV_OFF(st);

        // S = Q @ K^T  (already base-2 logits: Q pre-scaled)
        float s[8][4] = {};
        #pragma unroll
        for (int np = 0; np < 4; np++) {
            #pragma unroll
            for (int ks = 0; ks < 4; ks++) {
                uint32_t b0, b1, b2, b3;
                ldsm4(b0, b1, b2, b3, kb + bOff[np] + ks * 32);
                mma16(s[2 * np],     aq[ks], b0, b1);
                mma16(s[2 * np + 1], aq[ks], b2, b3);
            }
        }

        // Online softmax (base 2)
        float tmax0 = -1e30f, tmax1 = -1e30f;
        #pragma unroll
        for (int nt = 0; nt < 8; nt++) {
            tmax0 = fmaxf(tmax0, fmaxf(s[nt][0], s[nt][1]));
            tmax1 = fmaxf(tmax1, fmaxf(s[nt][2], s[nt][3]));
        }
        tmax0 = fmaxf(tmax0, __shfl_xor_sync(0xffffffffu, tmax0, 1));
        tmax0 = fmaxf(tmax0, __shfl_xor_sync(0xffffffffu, tmax0, 2));
        tmax1 = fmaxf(tmax1, __shfl_xor_sync(0xffffffffu, tmax1, 1));
        tmax1 = fmaxf(tmax1, __shfl_xor_sync(0xffffffffu, tmax1, 2));
        const float mn0 = fmaxf(mr[0], tmax0);
        const float mn1 = fmaxf(mr[1], tmax1);
        const float corr0 = exp2f(mr[0] - mn0);
        const float corr1 = exp2f(mr[1] - mn1);
        mr[0] = mn0; mr[1] = mn1;

        float rs0 = 0.f, rs1 = 0.f;
        #pragma unroll
        for (int nt = 0; nt < 8; nt++) {
            s[nt][0] = exp2f(s[nt][0] - mn0);
            s[nt][1] = exp2f(s[nt][1] - mn0);
            s[nt][2] = exp2f(s[nt][2] - mn1);
            s[nt][3] = exp2f(s[nt][3] - mn1);
            rs0 += s[nt][0] + s[nt][1];
            rs1 += s[nt][2] + s[nt][3];
        }
        rs0 += __shfl_xor_sync(0xffffffffu, rs0, 1);
        rs0 += __shfl_xor_sync(0xffffffffu, rs0, 2);
        rs1 += __shfl_xor_sync(0xffffffffu, rs1, 1);
        rs1 += __shfl_xor_sync(0xffffffffu, rs1, 2);
        lr_[0] = lr_[0] * corr0 + rs0;
        lr_[1] = lr_[1] * corr1 + rs1;

        #pragma unroll
        for (int nt = 0; nt < 8; nt++) {
            o[nt][0] *= corr0; o[nt][1] *= corr0;
            o[nt][2] *= corr1; o[nt][3] *= corr1;
        }

        // Repack S C-frags -> PV A-frags (register-only)
        uint32_t ap[4][4];
        #pragma unroll
        for (int ks = 0; ks < 4; ks++) {
            ap[ks][0] = packh2(s[2 * ks][0],     s[2 * ks][1]);
            ap[ks][1] = packh2(s[2 * ks][2],     s[2 * ks][3]);
            ap[ks][2] = packh2(s[2 * ks + 1][0], s[2 * ks + 1][1]);
            ap[ks][3] = packh2(s[2 * ks + 1][2], s[2 * ks + 1][3]);
        }

        // O += P @ V
        #pragma unroll
        for (int np = 0; np < 4; np++) {
            #pragma unroll
            for (int ks = 0; ks < 4; ks++) {
                uint32_t b0, b1, b2, b3;
                ldsm4(b0, b1, b2, b3, vb + bOff[np] + ks * 32);
                mma16(o[2 * np],     ap[ks], b0, b1);
                mma16(o[2 * np + 1], ap[ks], b2, b3);
            }
        }
    }

    // Normalize, write O as half to g_Xh [B,S,HID]
    const int b = bh >> 4, h = bh & 15;
    const int q = q0 + wid * 16 + qr;
    const float inv0 = 1.f / lr_[0];
    const float inv1 = 1.f / lr_[1];
    __half* base0 = g_Xh + (size_t)(b * SEQ + q) * HID + h * HD;
    __half* base1 = g_Xh + (size_t)(b * SEQ + q + 8) * HID + h * HD;
    #pragma unroll
    for (int nt = 0; nt < 8; nt++) {
        const int col = nt * 8 + 2 * qc;
        *(uint32_t*)(base0 + col) = packh2(o[nt][0] * inv0, o[nt][1] * inv0);
        *(uint32_t*)(base1 + col) = packh2(o[nt][2] * inv1, o[nt][3] * inv1);
    }
}

// ---------------------------------------------------------------------------
extern "C" void kernel_launch(void* const* d_in, const int* in_sizes, int n_in,
                              void* d_out, int out_size)
{
    const float* query = (const float*)d_in[0];
    const float* key   = (const float*)d_in[1];
    const float* value = (const float*)d_in[2];
    const float* wq    = (const float*)d_in[3];
    const float* bq    = (const float*)d_in[4];
    const float* wk    = (const float*)d_in[5];
    const float* bk    = (const float*)d_in[6];
    const float* wv    = (const float*)d_in[7];
    const float* bv    = (const float*)d_in[8];
    const float* wf    = (const float*)d_in[9];
    const float* bf    = (const float*)d_in[10];
    float* out = (float*)d_out;

    cudaFuncSetAttribute(gemm_h, cudaFuncAttributeMaxDynamicSharedMemorySize,
                         GEMM_SMEM);
    cudaFuncSetAttribute(attn_h, cudaFuncAttributeMaxDynamicSharedMemorySize,
                         ATTN_SMEM);

    cvt_h<<<(N4TOT + 255) / 256, 256>>>(query, key, value, wq, wk, wv, wf);

    dim3 gq(HID / 128, MTOT / 128, 3);
    gemm_h<<<gq, 256, GEMM_SMEM>>>(bq, bk, bv, nullptr, 0);

    dim3 ga(SEQ / 64, BATCH * NH);
    attn_h<<<ga, 128, ATTN_SMEM>>>();

    dim3 gf(HID / 128, MTOT / 128, 1);
    gemm_h<<<gf, 256, GEMM_SMEM>>>(bf, nullptr, nullptr, out, 1);
}

// round 9
// speedup vs baseline: 8.2337x; 1.1600x over previous
#include <cuda_runtime.h>
#include <cuda_fp16.h>
#include <cstdint>

#define HID   1024
#define NH    16
#define HD    64
#define BATCH 4
#define SEQ   2048
#define MTOT  (BATCH*SEQ)   // 8192

// Scratch (allocation-free rule: __device__ globals). All fp16.
__device__ __align__(16) __half h_Xq[(size_t)MTOT * HID];
__device__ __align__(16) __half h_Xk[(size_t)MTOT * HID];
__device__ __align__(16) __half h_Xv[(size_t)MTOT * HID];
__device__ __align__(16) __half h_Wq[(size_t)HID * HID];
__device__ __align__(16) __half h_Wk[(size_t)HID * HID];
__device__ __align__(16) __half h_Wv[(size_t)HID * HID];
__device__ __align__(16) __half h_Wf[(size_t)HID * HID];
__device__ __align__(16) __half g_Qh[(size_t)MTOT * HID];   // [B,H,S,D], pre-scaled
__device__ __align__(16) __half g_Kh[(size_t)MTOT * HID];   // [B,H,S,D]
__device__ __align__(16) __half g_Vt[(size_t)MTOT * HID];   // [B,H,D,S]  (transposed)
__device__ __align__(16) __half g_Xh[(size_t)MTOT * HID];   // [B,S,HID]

#define QSCALE (0.125f * 1.44269504f)   // 1/sqrt(64) * log2(e), folded into Q

// ---------------------------------------------------------------------------
static __device__ __forceinline__ uint32_t smem_u32(const void* p) {
    uint32_t a;
    asm("{ .reg .u64 t; cvta.to.shared.u64 t, %1; cvt.u32.u64 %0, t; }"
        : "=r"(a) : "l"(p));
    return a;
}
static __device__ __forceinline__ void mma16(float* d, const uint32_t* a,
                                             uint32_t b0, uint32_t b1) {
    asm volatile(
        "mma.sync.aligned.m16n8k16.row.col.f32.f16.f16.f32 "
        "{%0,%1,%2,%3}, {%4,%5,%6,%7}, {%8,%9}, {%0,%1,%2,%3};"
        : "+f"(d[0]), "+f"(d[1]), "+f"(d[2]), "+f"(d[3])
        : "r"(a[0]), "r"(a[1]), "r"(a[2]), "r"(a[3]), "r"(b0), "r"(b1));
}
static __device__ __forceinline__ void ldsm4(uint32_t& r0, uint32_t& r1,
                                             uint32_t& r2, uint32_t& r3,
                                             uint32_t addr) {
    asm volatile("ldmatrix.sync.aligned.m8n8.x4.shared.b16 {%0,%1,%2,%3}, [%4];"
                 : "=r"(r0), "=r"(r1), "=r"(r2), "=r"(r3) : "r"(addr));
}
static __device__ __forceinline__ uint32_t packh2(float x, float y) {
    __half2 h = __floats2half2_rn(x, y);
    return *(uint32_t*)&h;
}
#define CP16(dst, src) \
    asm volatile("cp.async.cg.shared.global [%0], [%1], 16;" :: "r"(dst), "l"(src) : "memory")
#define CP_COMMIT() asm volatile("cp.async.commit_group;" ::: "memory")
#define CP_WAIT1()  asm volatile("cp.async.wait_group 1;" ::: "memory")
#define CP_WAIT0()  asm volatile("cp.async.wait_group 0;" ::: "memory")

#define GROW 144
static __device__ __forceinline__ uint32_t lane_off_A(int lane) {
    return (uint32_t)(lane & 15) * GROW + (uint32_t)(lane >> 4) * 16;
}
static __device__ __forceinline__ uint32_t lane_off_B(int lane) {
    const int row = (lane & 7) + ((lane >> 4) & 1) * 8;
    const int colh = ((lane >> 3) & 1) * 8;
    return (uint32_t)row * GROW + (uint32_t)colh * 2;
}

// ---------------------------------------------------------------------------
// fp32 -> fp16 convert: 3 X inputs + 4 weights.
// ---------------------------------------------------------------------------
#define N4X (MTOT * HID / 4)
#define N4W (HID * HID / 4)
#define N4TOT (3 * N4X + 4 * N4W)

__global__ __launch_bounds__(256) void cvt_h(
    const float* __restrict__ q, const float* __restrict__ k,
    const float* __restrict__ v,
    const float* __restrict__ wq, const float* __restrict__ wk,
    const float* __restrict__ wv, const float* __restrict__ wf)
{
    const int id = blockIdx.x * 256 + threadIdx.x;
    if (id >= N4TOT) return;
    const float* src; __half* dst; int off;
    if (id < N4X)              { src = q;  dst = h_Xq; off = id; }
    else if (id < 2 * N4X)     { src = k;  dst = h_Xk; off = id - N4X; }
    else if (id < 3 * N4X)     { src = v;  dst = h_Xv; off = id - 2 * N4X; }
    else {
        int w = id - 3 * N4X;
        if (w < N4W)           { src = wq; dst = h_Wq; off = w; }
        else if (w < 2 * N4W)  { src = wk; dst = h_Wk; off = w - N4W; }
        else if (w < 3 * N4W)  { src = wv; dst = h_Wv; off = w - 2 * N4W; }
        else                   { src = wf; dst = h_Wf; off = w - 3 * N4W; }
    }
    float4 x = *(const float4*)(src + (size_t)off * 4);
    uint2 o;
    o.x = packh2(x.x, x.y);
    o.y = packh2(x.z, x.w);
    *(uint2*)(dst + (size_t)off * 4) = o;
}

// ---------------------------------------------------------------------------
// fp16 GEMM. CTA 128x128, BK=64, 256 thr = 8 warps (2m x 4n), warp tile 64x32.
// 3-stage cp.async, ldmatrix frag loads. 2 CTAs/SM -> 16 warps/SM.
// ---------------------------------------------------------------------------
#define GSTG  (2 * 128 * GROW)
#define GEMM_SMEM (3 * GSTG)              // 110592 B

__global__ __launch_bounds__(256, 2) void gemm_h(
    const float* __restrict__ Bq, const float* __restrict__ Bk,
    const float* __restrict__ Bv, float* __restrict__ outFinal, int mode)
{
    extern __shared__ char smc[];
    const uint32_t sbase = smem_u32(smc);

    const int which = (mode == 0) ? (int)blockIdx.z : 3;
    const __half* Xp; const __half* W; const float* bias;
    if (which == 0)      { Xp = h_Xq; W = h_Wq; bias = Bq; }
    else if (which == 1) { Xp = h_Xk; W = h_Wk; bias = Bk; }
    else if (which == 2) { Xp = h_Xv; W = h_Wv; bias = Bv; }
    else                 { Xp = g_Xh; W = h_Wf; bias = Bq; }

    const int tid  = threadIdx.x;
    const int wid  = tid >> 5;
    const int lane = tid & 31;
    const int wm   = wid & 1;
    const int wn   = wid >> 1;
    const int qr   = lane >> 2;
    const int qc   = lane & 3;
    const int m0   = blockIdx.y * 128;
    const int n0   = blockIdx.x * 128;

    auto issue = [&](int kc) {
        const uint32_t sA = sbase + (kc % 3) * GSTG;
        #pragma unroll
        for (int c = 0; c < 4; c++) {
            const int g   = c * 256 + tid;
            const int row = g >> 3;
            const int seg = g & 7;
            const uint32_t off = (uint32_t)row * GROW + seg * 16;
            CP16(sA + off, Xp + (size_t)(m0 + row) * HID + kc * 64 + seg * 8);
            CP16(sA + 128 * GROW + off,
                 W + (size_t)(n0 + row) * HID + kc * 64 + seg * 8);
        }
        CP_COMMIT();
    };

    const uint32_t offA = lane_off_A(lane);
    const uint32_t offB = lane_off_B(lane);
    uint32_t aAddr[4], bAddr[2];
    #pragma unroll
    for (int mt = 0; mt < 4; mt++)
        aAddr[mt] = (uint32_t)(wm * 64 + mt * 16) * GROW + offA;
    #pragma unroll
    for (int np = 0; np < 2; np++)
        bAddr[np] = 128 * GROW + (uint32_t)(wn * 32 + np * 16) * GROW + offB;

    float acc[4][4][4] = {};

    issue(0);
    issue(1);

    const int NKC = HID / 64;   // 16
    for (int kc = 0; kc < NKC; kc++) {
        if (kc + 1 < NKC) CP_WAIT1(); else CP_WAIT0();
        __syncthreads();
        if (kc + 2 < NKC) issue(kc + 2);

        const uint32_t stg = sbase + (kc % 3) * GSTG;
        #pragma unroll
        for (int ks = 0; ks < 4; ks++) {
            uint32_t af[4][4], bf[4][2];
            #pragma unroll
            for (int mt = 0; mt < 4; mt++)
                ldsm4(af[mt][0], af[mt][1], af[mt][2], af[mt][3],
                      stg + aAddr[mt] + ks * 32);
            #pragma unroll
            for (int np = 0; np < 2; np++)
                ldsm4(bf[2 * np][0], bf[2 * np][1], bf[2 * np + 1][0],
                      bf[2 * np + 1][1], stg + bAddr[np] + ks * 32);
            #pragma unroll
            for (int mt = 0; mt < 4; mt++)
                #pragma unroll
                for (int nt = 0; nt < 4; nt++)
                    mma16(acc[mt][nt], af[mt], bf[nt][0], bf[nt][1]);
        }
    }

    const float oscale = (which == 0) ? QSCALE : 1.0f;
    #pragma unroll
    for (int mt = 0; mt < 4; mt++) {
        const int m = m0 + wm * 64 + mt * 16 + qr;
        #pragma unroll
        for (int nt = 0; nt < 4; nt++) {
            const int n = n0 + wn * 32 + nt * 8 + 2 * qc;
            const float b0 = bias[n], b1 = bias[n + 1];
            const float v00 = acc[mt][nt][0] + b0, v01 = acc[mt][nt][1] + b1;
            const float v10 = acc[mt][nt][2] + b0, v11 = acc[mt][nt][3] + b1;
            if (which == 3) {
                *(float2*)(outFinal + (size_t)m * HID + n)       = make_float2(v00, v01);
                *(float2*)(outFinal + (size_t)(m + 8) * HID + n) = make_float2(v10, v11);
            } else {
                const int bb = m >> 11, s = m & 2047;
                const int h = n >> 6,  d = n & 63;
                if (which == 2) {
                    __half* base = g_Vt + ((size_t)(bb * NH + h) * HD) * SEQ;
                    base[(size_t)(d + 0) * SEQ + s]     = __float2half(v00);
                    base[(size_t)(d + 1) * SEQ + s]     = __float2half(v01);
                    base[(size_t)(d + 0) * SEQ + s + 8] = __float2half(v10);
                    base[(size_t)(d + 1) * SEQ + s + 8] = __float2half(v11);
                } else {
                    __half* outh = (which == 0) ? g_Qh : g_Kh;
                    __half* base = outh + ((size_t)(bb * NH + h) * SEQ) * HD + d;
                    *(uint32_t*)(base + (size_t)s * HD) =
                        packh2(v00 * oscale, v01 * oscale);
                    *(uint32_t*)(base + (size_t)(s + 8) * HD) =
                        packh2(v10 * oscale, v11 * oscale);
                }
            }
        }
    }
}

// ---------------------------------------------------------------------------
// fp16 flash attention. Br=128 q rows/CTA (256 thr, 8 warps), Bc=64.
// Each K/V tile now serves 128 q rows -> K/V gmem+L2 traffic halved vs Br=64.
// Q pre-scaled; K natural [kv][d]; V transposed [d][kv]; P register-only.
// smem: Q 128*144 + 2 stages * (K 64*144 + V 64*144) = 55296 B.
// ---------------------------------------------------------------------------
#define AQ_OFF 0
#define AK_OFF(st) (18432 + (st) * 18432)
#define AV_OFF(st) (AK_OFF(st) + 9216)
#define ATTN_SMEM 55296

__global__ __launch_bounds__(256, 2) void attn_h()
{
    extern __shared__ char smc[];
    const uint32_t sbase = smem_u32(smc);

    const int tid  = threadIdx.x;
    const int wid  = tid >> 5;        // 0..7 -> q rows [wid*16, wid*16+16)
    const int lane = tid & 31;
    const int qr   = lane >> 2;
    const int qc   = lane & 3;
    const int q0   = blockIdx.x * 128;
    const int bh   = blockIdx.y;

    const __half* Qg  = g_Qh + (size_t)bh * SEQ * HD;
    const __half* Kg  = g_Kh + (size_t)bh * SEQ * HD;
    const __half* Vtg = g_Vt + (size_t)bh * HD * SEQ;

    // Q tile: 128 rows x 64 halves. 256 thr: thread -> row tid>>1, half-row seg.
    {
        const int cr = tid >> 1, cs = tid & 1;
        #pragma unroll
        for (int i = 0; i < 4; i++)
            CP16(sbase + AQ_OFF + (uint32_t)cr * GROW + cs * 64 + i * 16,
                 Qg + (size_t)(q0 + cr) * HD + cs * 32 + i * 8);
        CP_COMMIT();
    }

    // K/V tiles: 64 rows x 64 halves each. thread -> row tid>>2, quarter-row seg.
    const int kr = tid >> 2, ks4 = tid & 3;
    auto issueKV = [&](int kt, int st) {
        #pragma unroll
        for (int i = 0; i < 2; i++) {
            CP16(sbase + AK_OFF(st) + (uint32_t)kr * GROW + ks4 * 32 + i * 16,
                 Kg + (size_t)(kt + kr) * HD + ks4 * 16 + i * 8);
            CP16(sbase + AV_OFF(st) + (uint32_t)kr * GROW + ks4 * 32 + i * 16,
                 Vtg + (size_t)kr * SEQ + kt + ks4 * 16 + i * 8);
        }
        CP_COMMIT();
    };

    issueKV(0, 0);
    CP_WAIT1();        // Q ready
    __syncthreads();

    const uint32_t offA = lane_off_A(lane);
    const uint32_t offB = lane_off_B(lane);

    // Hoist this warp's Q A-fragments for the whole kernel
    uint32_t aq[4][4];
    {
        const uint32_t qa = sbase + AQ_OFF + (uint32_t)(wid * 16) * GROW + offA;
        #pragma unroll
        for (int ks = 0; ks < 4; ks++)
            ldsm4(aq[ks][0], aq[ks][1], aq[ks][2], aq[ks][3], qa + ks * 32);
    }

    uint32_t bOff[4];
    #pragma unroll
    for (int np = 0; np < 4; np++)
        bOff[np] = (uint32_t)(np * 16) * GROW + offB;

    float o[8][4] = {};
    float mr[2] = { -1e30f, -1e30f };
    float lr_[2] = { 0.f, 0.f };

    const int NT = SEQ / 64;   // 32
    for (int t = 0; t < NT; t++) {
        const int st = t & 1;
        __syncthreads();
        if (t + 1 < NT) { issueKV((t + 1) * 64, st ^ 1); CP_WAIT1(); }
        else            { CP_WAIT0(); }
        __syncthreads();

        const uint32_t kb = sbase + AK_OFF(st);
        const uint32_t vb = sbase + AV_OFF(st);

        // S = Q @ K^T  (base-2 logits already)
        float s[8][4] = {};
        #pragma unroll
        for (int np = 0; np < 4; np++) {
            #pragma unroll
            for (int ks = 0; ks < 4; ks++) {
                uint32_t b0, b1, b2, b3;
                ldsm4(b0, b1, b2, b3, kb + bOff[np] + ks * 32);
                mma16(s[2 * np],     aq[ks], b0, b1);
                mma16(s[2 * np + 1], aq[ks], b2, b3);
            }
        }

        // Online softmax (base 2)
        float tmax0 = -1e30f, tmax1 = -1e30f;
        #pragma unroll
        for (int nt = 0; nt < 8; nt++) {
            tmax0 = fmaxf(tmax0, fmaxf(s[nt][0], s[nt][1]));
            tmax1 = fmaxf(tmax1, fmaxf(s[nt][2], s[nt][3]));
        }
        tmax0 = fmaxf(tmax0, __shfl_xor_sync(0xffffffffu, tmax0, 1));
        tmax0 = fmaxf(tmax0, __shfl_xor_sync(0xffffffffu, tmax0, 2));
        tmax1 = fmaxf(tmax1, __shfl_xor_sync(0xffffffffu, tmax1, 1));
        tmax1 = fmaxf(tmax1, __shfl_xor_sync(0xffffffffu, tmax1, 2));
        const float mn0 = fmaxf(mr[0], tmax0);
        const float mn1 = fmaxf(mr[1], tmax1);
        const float corr0 = exp2f(mr[0] - mn0);
        const float corr1 = exp2f(mr[1] - mn1);
        mr[0] = mn0; mr[1] = mn1;

        float rs0 = 0.f, rs1 = 0.f;
        #pragma unroll
        for (int nt = 0; nt < 8; nt++) {
            s[nt][0] = exp2f(s[nt][0] - mn0);
            s[nt][1] = exp2f(s[nt][1] - mn0);
            s[nt][2] = exp2f(s[nt][2] - mn1);
            s[nt][3] = exp2f(s[nt][3] - mn1);
            rs0 += s[nt][0] + s[nt][1];
            rs1 += s[nt][2] + s[nt][3];
        }
        rs0 += __shfl_xor_sync(0xffffffffu, rs0, 1);
        rs0 += __shfl_xor_sync(0xffffffffu, rs0, 2);
        rs1 += __shfl_xor_sync(0xffffffffu, rs1, 1);
        rs1 += __shfl_xor_sync(0xffffffffu, rs1, 2);
        lr_[0] = lr_[0] * corr0 + rs0;
        lr_[1] = lr_[1] * corr1 + rs1;

        #pragma unroll
        for (int nt = 0; nt < 8; nt++) {
            o[nt][0] *= corr0; o[nt][1] *= corr0;
            o[nt][2] *= corr1; o[nt][3] *= corr1;
        }

        // Repack S C-frags -> PV A-frags (register-only)
        uint32_t ap[4][4];
        #pragma unroll
        for (int ks = 0; ks < 4; ks++) {
            ap[ks][0] = packh2(s[2 * ks][0],     s[2 * ks][1]);
            ap[ks][1] = packh2(s[2 * ks][2],     s[2 * ks][3]);
            ap[ks][2] = packh2(s[2 * ks + 1][0], s[2 * ks + 1][1]);
            ap[ks][3] = packh2(s[2 * ks + 1][2], s[2 * ks + 1][3]);
        }

        // O += P @ V
        #pragma unroll
        for (int np = 0; np < 4; np++) {
            #pragma unroll
            for (int ks = 0; ks < 4; ks++) {
                uint32_t b0, b1, b2, b3;
                ldsm4(b0, b1, b2, b3, vb + bOff[np] + ks * 32);
                mma16(o[2 * np],     ap[ks], b0, b1);
                mma16(o[2 * np + 1], ap[ks], b2, b3);
            }
        }
    }

    // Normalize, write O as half to g_Xh [B,S,HID]
    const int b = bh >> 4, h = bh & 15;
    const int q = q0 + wid * 16 + qr;
    const float inv0 = 1.f / lr_[0];
    const float inv1 = 1.f / lr_[1];
    __half* base0 = g_Xh + (size_t)(b * SEQ + q) * HID + h * HD;
    __half* base1 = g_Xh + (size_t)(b * SEQ + q + 8) * HID + h * HD;
    #pragma unroll
    for (int nt = 0; nt < 8; nt++) {
        const int col = nt * 8 + 2 * qc;
        *(uint32_t*)(base0 + col) = packh2(o[nt][0] * inv0, o[nt][1] * inv0);
        *(uint32_t*)(base1 + col) = packh2(o[nt][2] * inv1, o[nt][3] * inv1);
    }
}

// ---------------------------------------------------------------------------
extern "C" void kernel_launch(void* const* d_in, const int* in_sizes, int n_in,
                              void* d_out, int out_size)
{
    const float* query = (const float*)d_in[0];
    const float* key   = (const float*)d_in[1];
    const float* value = (const float*)d_in[2];
    const float* wq    = (const float*)d_in[3];
    const float* bq    = (const float*)d_in[4];
    const float* wk    = (const float*)d_in[5];
    const float* bk    = (const float*)d_in[6];
    const float* wv    = (const float*)d_in[7];
    const float* bv    = (const float*)d_in[8];
    const float* wf    = (const float*)d_in[9];
    const float* bf    = (const float*)d_in[10];
    float* out = (float*)d_out;

    cudaFuncSetAttribute(gemm_h, cudaFuncAttributeMaxDynamicSharedMemorySize,
                         GEMM_SMEM);
    cudaFuncSetAttribute(attn_h, cudaFuncAttributeMaxDynamicSharedMemorySize,
                         ATTN_SMEM);

    cvt_h<<<(N4TOT + 255) / 256, 256>>>(query, key, value, wq, wk, wv, wf);

    dim3 gq(HID / 128, MTOT / 128, 3);
    gemm_h<<<gq, 256, GEMM_SMEM>>>(bq, bk, bv, nullptr, 0);

    dim3 ga(SEQ / 128, BATCH * NH);   // (16, 64)
    attn_h<<<ga, 256, ATTN_SMEM>>>();

    dim3 gf(HID / 128, MTOT / 128, 1);
    gemm_h<<<gf, 256, GEMM_SMEM>>>(bf, nullptr, nullptr, out, 1);
}